// round 2
// baseline (speedup 1.0000x reference)
#include <cuda_runtime.h>
#include <math.h>

#define SZ 65535
#define TM 64
#define NTHREADS 256

// shared memory layout (floats)
#define OFF_OBS 0        // 64 x 260
#define OFF_W   16640    // 64 x 132  (weight staging)
#define OFF_X   25088    // 64 x 132
#define OFF_H   33536    // 64 x 132
#define OFF_V   41984    // 64 x 68
#define SMEM_FLOATS 46336
#define SMEM_BYTES (SMEM_FLOATS * 4)

__device__ __forceinline__ float sgm(float x) { return 1.0f / (1.0f + __expf(-x)); }

// C[8][4] += A_s[64 rows][LDA] cols [0..63] (caller offsets As by k0) * B_s[64][132]
template <int LDA>
__device__ __forceinline__ void gemm_chunk(const float* __restrict__ As,
                                           const float* __restrict__ Bs,
                                           float acc[8][4], int ty, int tx) {
    const int r0 = ty * 8;
#pragma unroll 2
    for (int kk = 0; kk < 64; kk += 4) {
        float b[4][4];
#pragma unroll
        for (int q = 0; q < 4; q++) {
            float4 t = *(const float4*)(Bs + (kk + q) * 132 + tx * 4);
            b[q][0] = t.x; b[q][1] = t.y; b[q][2] = t.z; b[q][3] = t.w;
        }
#pragma unroll
        for (int i = 0; i < 8; i++) {
            float4 a = *(const float4*)(As + (r0 + i) * LDA + kk);
#pragma unroll
            for (int j = 0; j < 4; j++) {
                acc[i][j] += a.x * b[0][j];
                acc[i][j] += a.y * b[1][j];
                acc[i][j] += a.z * b[2][j];
                acc[i][j] += a.w * b[3][j];
            }
        }
    }
}

// Stage Bs[kk][n] = W[nbase + n][k0 + kk], kk<64, n<128 (k-major in smem, stride 132)
__device__ __forceinline__ void stage128(const float* __restrict__ W, int ldw,
                                         int nbase, int k0,
                                         float* __restrict__ Bs, int tid) {
#pragma unroll
    for (int j = 0; j < 8; j++) {
        int e = tid + j * 256;
        int n = e & 127;
        int kk4 = e >> 7;  // 0..15
        float4 w = *(const float4*)(W + (size_t)(nbase + n) * ldw + k0 + kk4 * 4);
        Bs[(kk4 * 4 + 0) * 132 + n] = w.x;
        Bs[(kk4 * 4 + 1) * 132 + n] = w.y;
        Bs[(kk4 * 4 + 2) * 132 + n] = w.z;
        Bs[(kk4 * 4 + 3) * 132 + n] = w.w;
    }
}

// Stage Bs[kk][n] = W[n][k0 + kk], kk<64, n<64 (stride 68)
__device__ __forceinline__ void stage64(const float* __restrict__ W, int k0,
                                        float* __restrict__ Bs, int tid) {
#pragma unroll
    for (int j = 0; j < 4; j++) {
        int e = tid + j * 256;
        int n = e & 63;
        int kk4 = e >> 6;  // 0..15
        float4 w = *(const float4*)(W + (size_t)n * 128 + k0 + kk4 * 4);
        Bs[(kk4 * 4 + 0) * 68 + n] = w.x;
        Bs[(kk4 * 4 + 1) * 68 + n] = w.y;
        Bs[(kk4 * 4 + 2) * 68 + n] = w.z;
        Bs[(kk4 * 4 + 3) * 68 + n] = w.w;
    }
}

__global__ void __launch_bounds__(NTHREADS, 1)
attention_critic_kernel(const float* __restrict__ obs,
                        const float* __restrict__ hid,
                        const float* __restrict__ enc_w,
                        const float* __restrict__ enc_b,
                        const float* __restrict__ w_ih,
                        const float* __restrict__ w_hh,
                        const float* __restrict__ b_ih,
                        const float* __restrict__ b_hh,
                        const float* __restrict__ v_w,
                        const float* __restrict__ v_b,
                        const float* __restrict__ dec_w,
                        const float* __restrict__ dec_b,
                        float* __restrict__ out,
                        float* __restrict__ hout_g) {
    extern __shared__ float sm[];
    float* s_obs = sm + OFF_OBS;
    float* s_w   = sm + OFF_W;
    float* s_x   = sm + OFF_X;
    float* s_h   = sm + OFF_H;
    float* s_v   = sm + OFF_V;
    float* s_ho  = s_obs;  // obs tile dead after enc GEMM

    const int tid = threadIdx.x;
    const int tx = tid & 31;
    const int ty = tid >> 5;
    const int row0 = blockIdx.x * TM;

    // ---- load obs tile [64][256] and hidden tile [64][128] ----
#pragma unroll
    for (int j = 0; j < 16; j++) {
        int e = tid + j * 256;          // 0..4095
        int r = e >> 6, c4 = e & 63;
        int gr = row0 + r;
        float4 val = make_float4(0.f, 0.f, 0.f, 0.f);
        if (gr < SZ) val = *(const float4*)(obs + (size_t)gr * 256 + c4 * 4);
        *(float4*)(s_obs + r * 260 + c4 * 4) = val;
    }
#pragma unroll
    for (int j = 0; j < 8; j++) {
        int e = tid + j * 256;          // 0..2047
        int r = e >> 5, c4 = e & 31;
        int gr = row0 + r;
        float4 val = make_float4(0.f, 0.f, 0.f, 0.f);
        if (gr < SZ) val = *(const float4*)(hid + (size_t)gr * 128 + c4 * 4);
        *(float4*)(s_h + r * 132 + c4 * 4) = val;
    }

    float acc[8][4];

    // ---- enc: x = relu(obs @ enc_w^T + enc_b) ----
#pragma unroll
    for (int i = 0; i < 8; i++)
#pragma unroll
        for (int j = 0; j < 4; j++) acc[i][j] = 0.f;

    for (int k0 = 0; k0 < 256; k0 += 64) {
        __syncthreads();
        stage128(enc_w, 256, 0, k0, s_w, tid);
        __syncthreads();
        gemm_chunk<260>(s_obs + k0, s_w, acc, ty, tx);   // FIX: A advances with k0
    }
    {
        float b0 = enc_b[tx * 4 + 0], b1 = enc_b[tx * 4 + 1];
        float b2 = enc_b[tx * 4 + 2], b3 = enc_b[tx * 4 + 3];
#pragma unroll
        for (int i = 0; i < 8; i++) {
            float* dst = s_x + (ty * 8 + i) * 132 + tx * 4;
            dst[0] = fmaxf(acc[i][0] + b0, 0.f);
            dst[1] = fmaxf(acc[i][1] + b1, 0.f);
            dst[2] = fmaxf(acc[i][2] + b2, 0.f);
            dst[3] = fmaxf(acc[i][3] + b3, 0.f);
        }
    }

    // ---- GRU cell ----
    float rg[8][4], zg[8][4], gi[8][4];
#pragma unroll
    for (int c = 0; c < 3; c++) {
        // gi_c = x @ w_ih[c*128:(c+1)*128]^T
#pragma unroll
        for (int i = 0; i < 8; i++)
#pragma unroll
            for (int j = 0; j < 4; j++) acc[i][j] = 0.f;
        for (int k0 = 0; k0 < 128; k0 += 64) {
            __syncthreads();
            stage128(w_ih, 128, c * 128, k0, s_w, tid);
            __syncthreads();
            gemm_chunk<132>(s_x + k0, s_w, acc, ty, tx);  // FIX
        }
#pragma unroll
        for (int i = 0; i < 8; i++)
#pragma unroll
            for (int j = 0; j < 4; j++) gi[i][j] = acc[i][j];

        // gh_c = h @ w_hh[c*128:(c+1)*128]^T
#pragma unroll
        for (int i = 0; i < 8; i++)
#pragma unroll
            for (int j = 0; j < 4; j++) acc[i][j] = 0.f;
        for (int k0 = 0; k0 < 128; k0 += 64) {
            __syncthreads();
            stage128(w_hh, 128, c * 128, k0, s_w, tid);
            __syncthreads();
            gemm_chunk<132>(s_h + k0, s_w, acc, ty, tx);  // FIX
        }

        float bi0 = b_ih[c * 128 + tx * 4 + 0], bh0 = b_hh[c * 128 + tx * 4 + 0];
        float bi1 = b_ih[c * 128 + tx * 4 + 1], bh1 = b_hh[c * 128 + tx * 4 + 1];
        float bi2 = b_ih[c * 128 + tx * 4 + 2], bh2 = b_hh[c * 128 + tx * 4 + 2];
        float bi3 = b_ih[c * 128 + tx * 4 + 3], bh3 = b_hh[c * 128 + tx * 4 + 3];

#pragma unroll
        for (int i = 0; i < 8; i++) {
            float giv[4], ghv[4];
            giv[0] = gi[i][0] + bi0; ghv[0] = acc[i][0] + bh0;
            giv[1] = gi[i][1] + bi1; ghv[1] = acc[i][1] + bh1;
            giv[2] = gi[i][2] + bi2; ghv[2] = acc[i][2] + bh2;
            giv[3] = gi[i][3] + bi3; ghv[3] = acc[i][3] + bh3;
            if (c == 0) {
#pragma unroll
                for (int j = 0; j < 4; j++) rg[i][j] = sgm(giv[j] + ghv[j]);
            } else if (c == 1) {
#pragma unroll
                for (int j = 0; j < 4; j++) zg[i][j] = sgm(giv[j] + ghv[j]);
            } else {
                float ho[4];
#pragma unroll
                for (int j = 0; j < 4; j++) {
                    float n = tanhf(giv[j] + rg[i][j] * ghv[j]);
                    float h = s_h[(ty * 8 + i) * 132 + tx * 4 + j];
                    ho[j] = (1.f - zg[i][j]) * n + zg[i][j] * h;
                }
                float* dst = s_ho + (ty * 8 + i) * 132 + tx * 4;
                dst[0] = ho[0]; dst[1] = ho[1]; dst[2] = ho[2]; dst[3] = ho[3];
                int gr = row0 + ty * 8 + i;
                if (gr < SZ) {
                    float* g = hout_g + (size_t)gr * 128 + tx * 4;
                    *(float2*)(g + 0) = make_float2(ho[0], ho[1]);
                    *(float2*)(g + 2) = make_float2(ho[2], ho[3]);
                }
            }
        }
    }

    // ---- v = relu(h_out @ v_w^T + v_b) ----
    float vacc[8][2];
#pragma unroll
    for (int i = 0; i < 8; i++) { vacc[i][0] = 0.f; vacc[i][1] = 0.f; }
    for (int k0 = 0; k0 < 128; k0 += 64) {
        __syncthreads();
        stage64(v_w, k0, s_w, tid);
        __syncthreads();
        const int r0 = ty * 8;
        const float* Aho = s_ho + k0;                      // FIX: A advances with k0
#pragma unroll 2
        for (int kk = 0; kk < 64; kk += 4) {
            float b[4][2];
#pragma unroll
            for (int q = 0; q < 4; q++) {
                float2 t = *(const float2*)(s_w + (kk + q) * 68 + tx * 2);
                b[q][0] = t.x; b[q][1] = t.y;
            }
#pragma unroll
            for (int i = 0; i < 8; i++) {
                float4 a = *(const float4*)(Aho + (r0 + i) * 132 + kk);
                vacc[i][0] += a.x * b[0][0] + a.y * b[1][0] + a.z * b[2][0] + a.w * b[3][0];
                vacc[i][1] += a.x * b[0][1] + a.y * b[1][1] + a.z * b[2][1] + a.w * b[3][1];
            }
        }
    }
    {
        float vb0 = v_b[tx * 2 + 0], vb1 = v_b[tx * 2 + 1];
#pragma unroll
        for (int i = 0; i < 8; i++) {
            float* dst = s_v + (ty * 8 + i) * 68 + tx * 2;
            dst[0] = fmaxf(vacc[i][0] + vb0, 0.f);
            dst[1] = fmaxf(vacc[i][1] + vb1, 0.f);
        }
    }
    __syncthreads();

    // ---- decoder: out = [h_out, v] @ dec_w^T + dec_b ----
    for (int e = tid; e < TM * 10; e += NTHREADS) {
        int r = e / 10;
        int c = e - r * 10;
        float sum = dec_b[c];
        const float4* dw = (const float4*)(dec_w + c * 192);
        const float4* hr = (const float4*)(s_ho + r * 132);
#pragma unroll
        for (int k4 = 0; k4 < 32; k4++) {
            float4 d = dw[k4], h = hr[k4];
            sum += d.x * h.x + d.y * h.y + d.z * h.z + d.w * h.w;
        }
        const float4* dv = (const float4*)(dec_w + c * 192 + 128);
        const float4* vr = (const float4*)(s_v + r * 68);
#pragma unroll
        for (int k4 = 0; k4 < 16; k4++) {
            float4 d = dv[k4], v = vr[k4];
            sum += d.x * v.x + d.y * v.y + d.z * v.z + d.w * v.w;
        }
        int gr = row0 + r;
        if (gr < SZ) out[(size_t)gr * 10 + c] = sum;
    }
}

extern "C" void kernel_launch(void* const* d_in, const int* in_sizes, int n_in,
                              void* d_out, int out_size) {
    const float* obs   = (const float*)d_in[0];
    const float* hid   = (const float*)d_in[1];
    const float* enc_w = (const float*)d_in[2];
    const float* enc_b = (const float*)d_in[3];
    const float* w_ih  = (const float*)d_in[4];
    const float* w_hh  = (const float*)d_in[5];
    const float* b_ih  = (const float*)d_in[6];
    const float* b_hh  = (const float*)d_in[7];
    const float* v_w   = (const float*)d_in[20];
    const float* v_b   = (const float*)d_in[21];
    const float* dec_w = (const float*)d_in[22];
    const float* dec_b = (const float*)d_in[23];

    float* out  = (float*)d_out;
    float* hout = out + (size_t)SZ * 10;  // tuple (output, h_out) flattened in order

    cudaFuncSetAttribute(attention_critic_kernel,
                         cudaFuncAttributeMaxDynamicSharedMemorySize, SMEM_BYTES);

    int grid = (SZ + TM - 1) / TM;  // 1024
    attention_critic_kernel<<<grid, NTHREADS, SMEM_BYTES>>>(
        obs, hid, enc_w, enc_b, w_ih, w_hh, b_ih, b_hh,
        v_w, v_b, dec_w, dec_b, out, hout);
}

// round 4
// speedup vs baseline: 2.7059x; 2.7059x over previous
#include <cuda_runtime.h>
#include <cuda_bf16.h>
#include <math.h>
#include <stdint.h>

#define SZ 65535
#define THREADS 256
#define GRID 512

// ---- weight fragment image offsets (uint4 units) ----
#define ENC_F   0        // 8 n2 x 16 kt x 32
#define WIHR_F  4096     // 8 n2 x 8 kt x 32
#define WIHZ_F  6144
#define WIHN_F  8192
#define WHHR_F  10240
#define WHHZ_F  12288
#define WHHN_F  14336
#define VW_F    16384    // 4 n2 x 8 kt x 32
#define DEC_F   17408    // 1 n2 x 12 kt x 32
#define FRAG_TOTAL 17792

__device__ __align__(16) uint4 g_bh[FRAG_TOTAL];
__device__ __align__(16) uint4 g_bl[FRAG_TOTAL];

// ---- SMEM layout (bytes). Activation regions: per 64-col K block: hi 16KB, lo 16KB ----
#define OFF_X    0        // 64KB: x splits (2 blocks), then h_out splits
#define OFF_H    65536    // 64KB: h splits (2 blocks); later v splits (block 0)
#define OFF_OBS  131072   // 32KB: obs staging (1 block)
#define OFF_BR   163840
#define OFF_BZ   164352
#define OFF_BIN  164864
#define OFF_BHN  165376
#define OFF_ENCB 165888
#define OFF_VB   166400
#define OFF_DECB 166656
#define SMEM_TOTAL 166784

#define SWZ(o) ((o) ^ (((o) >> 3) & 0x70))

__device__ __forceinline__ uint32_t smem_u32(const void* p) {
    uint32_t a;
    asm("{ .reg .u64 t; cvta.to.shared.u64 t, %1; cvt.u32.u64 %0, t; }" : "=r"(a) : "l"(p));
    return a;
}

__device__ __forceinline__ void ldm4(uint32_t r[4], uint32_t a) {
    asm volatile("ldmatrix.sync.aligned.m8n8.x4.shared.b16 {%0,%1,%2,%3}, [%4];"
        : "=r"(r[0]), "=r"(r[1]), "=r"(r[2]), "=r"(r[3]) : "r"(a));
}

__device__ __forceinline__ void mma_bf16(float c[4], const uint32_t a[4], uint32_t b0, uint32_t b1) {
    asm volatile("mma.sync.aligned.m16n8k16.row.col.f32.bf16.bf16.f32 "
        "{%0,%1,%2,%3}, {%4,%5,%6,%7}, {%8,%9}, {%0,%1,%2,%3};"
        : "+f"(c[0]), "+f"(c[1]), "+f"(c[2]), "+f"(c[3])
        : "r"(a[0]), "r"(a[1]), "r"(a[2]), "r"(a[3]), "r"(b0), "r"(b1));
}

// 3-term split mma for an n16 pair (even/odd ntile)
__device__ __forceinline__ void mma3(float cE[4], float cO[4],
                                     const uint32_t ah[4], const uint32_t al[4],
                                     uint4 Bh, uint4 Bl) {
    mma_bf16(cE, ah, Bh.x, Bh.z);
    mma_bf16(cE, ah, Bl.x, Bl.z);
    mma_bf16(cE, al, Bh.x, Bh.z);
    mma_bf16(cO, ah, Bh.y, Bh.w);
    mma_bf16(cO, ah, Bl.y, Bl.w);
    mma_bf16(cO, al, Bh.y, Bh.w);
}

__device__ __forceinline__ uint32_t pack2(float a, float b, uint32_t& lo) {
    __nv_bfloat16 ah = __float2bfloat16_rn(a), bh = __float2bfloat16_rn(b);
    float ar = a - __bfloat162float(ah), br = b - __bfloat162float(bh);
    __nv_bfloat16 al = __float2bfloat16_rn(ar), bl = __float2bfloat16_rn(br);
    lo = (uint32_t)__bfloat16_as_ushort(al) | ((uint32_t)__bfloat16_as_ushort(bl) << 16);
    return (uint32_t)__bfloat16_as_ushort(ah) | ((uint32_t)__bfloat16_as_ushort(bh) << 16);
}

__device__ __forceinline__ float bf_lo(uint32_t v) {
    return __bfloat162float(__ushort_as_bfloat16((unsigned short)(v & 0xFFFF)));
}
__device__ __forceinline__ float bf_hi(uint32_t v) {
    return __bfloat162float(__ushort_as_bfloat16((unsigned short)(v >> 16)));
}

__device__ __forceinline__ float sigm(float x) { return 1.f / (1.f + __expf(-x)); }

// store split pair (col even) into activation region (blocked hi/lo layout)
__device__ __forceinline__ void store_pair_split(char* region, int row, int col, float a, float b) {
    uint32_t lo;
    uint32_t hi = pack2(a, b, lo);
    uint32_t off = (uint32_t)((col >> 6) * 32768) + SWZ((uint32_t)(row * 128 + (col & 63) * 2));
    *(uint32_t*)(region + off) = hi;
    *(uint32_t*)(region + 16384 + off) = lo;
}

// convert [128 rows x 64 cols] fp32 gmem tile -> bf16 hi/lo swizzled planes
__device__ void conv_tile(const float* __restrict__ g, int stride, int col0, int row0g,
                          char* bhi, char* blo, int tid) {
#pragma unroll
    for (int i = 0; i < 4; i++) {
        int t = tid + i * 256;
        int r = t >> 3, gi = t & 7;
        int gr = row0g + r;
        float x[8];
        if (gr < SZ) {
            float4 a = *(const float4*)(g + (size_t)gr * stride + col0 + gi * 8);
            float4 b = *(const float4*)(g + (size_t)gr * stride + col0 + gi * 8 + 4);
            x[0]=a.x; x[1]=a.y; x[2]=a.z; x[3]=a.w; x[4]=b.x; x[5]=b.y; x[6]=b.z; x[7]=b.w;
        } else {
#pragma unroll
            for (int j = 0; j < 8; j++) x[j] = 0.f;
        }
        uint32_t off = SWZ((uint32_t)(r * 128 + gi * 16));
        uint4 H, L;
        uint32_t l0, l1, l2, l3;
        H.x = pack2(x[0], x[1], l0); H.y = pack2(x[2], x[3], l1);
        H.z = pack2(x[4], x[5], l2); H.w = pack2(x[6], x[7], l3);
        L.x = l0; L.y = l1; L.z = l2; L.w = l3;
        *(uint4*)(bhi + off) = H;
        *(uint4*)(blo + off) = L;
    }
}

// ---------------- prep: pack all weights as bf16 hi/lo mma B-fragments ----------------
__global__ void prep_kernel(const float* __restrict__ enc_w, const float* __restrict__ w_ih,
                            const float* __restrict__ w_hh, const float* __restrict__ v_w,
                            const float* __restrict__ dec_w) {
    int idx = blockIdx.x * blockDim.x + threadIdx.x;
    if (idx >= FRAG_TOTAL) return;
    const float* W; int ldw, nmax, ktc, base;
    if (idx < 4096)       { W = enc_w; ldw = 256; nmax = 128; base = 0; ktc = 16; }
    else if (idx < 10240) { int g = (idx - 4096) / 2048; W = w_ih + (size_t)g * 128 * 128;
                            ldw = 128; nmax = 128; base = 4096 + g * 2048; ktc = 8; }
    else if (idx < 16384) { int g = (idx - 10240) / 2048; W = w_hh + (size_t)g * 128 * 128;
                            ldw = 128; nmax = 128; base = 10240 + g * 2048; ktc = 8; }
    else if (idx < 17408) { W = v_w; ldw = 128; nmax = 64; base = 16384; ktc = 8; }
    else                  { W = dec_w; ldw = 192; nmax = 10; base = 17408; ktc = 12; }

    int local = idx - base;
    int n2 = local / (ktc * 32);
    int rem = local - n2 * ktc * 32;
    int kt = rem >> 5, lane = rem & 31;
    int n = n2 * 16 + (lane >> 2);
    int k = kt * 16 + (lane & 3) * 2;

    float w[8];
#pragma unroll
    for (int dn = 0; dn < 2; dn++)
#pragma unroll
        for (int dk = 0; dk < 2; dk++)
#pragma unroll
            for (int e = 0; e < 2; e++) {
                int nn = n + dn * 8, kk = k + dk * 8 + e;
                w[(dn + dk * 2) * 2 + e] = (nn < nmax) ? W[(size_t)nn * ldw + kk] : 0.f;
            }
    // reg order: r0=(n,k) r1=(n+8,k) r2=(n,k+8) r3=(n+8,k+8)
    uint4 H, L;
    uint32_t l0, l1, l2, l3;
    H.x = pack2(w[0], w[1], l0);   // dn0 dk0
    H.y = pack2(w[2], w[3], l1);   // dn1 dk0
    H.z = pack2(w[4], w[5], l2);   // dn0 dk1
    H.w = pack2(w[6], w[7], l3);   // dn1 dk1
    L.x = l0; L.y = l1; L.z = l2; L.w = l3;
    g_bh[idx] = H;
    g_bl[idx] = L;
}

// GRU gate gemm: acc[8][4] += A(region rows mrow..mrow+16, K=128) @ Wfrag^T (warp's 64-col strip)
__device__ __forceinline__ void gemm_gate(float acc[8][4], uint32_t areg, int mrow,
                                          int wn, int lane, int fragbase) {
    const int arow = mrow + (lane & 15);
    const int kkp = (lane >> 4) << 3;
#pragma unroll
    for (int kt = 0; kt < 8; kt++) {
        int kk = kt * 16 + kkp;
        uint32_t off = (uint32_t)((kk >> 6) * 32768) + SWZ((uint32_t)(arow * 128 + (kk & 63) * 2));
        uint32_t ah[4], al[4];
        ldm4(ah, areg + off);
        ldm4(al, areg + 16384 + off);
#pragma unroll
        for (int l = 0; l < 4; l++) {
            int fi = fragbase + ((wn * 4 + l) * 8 + kt) * 32 + lane;
            uint4 Bh = g_bh[fi], Bl = g_bl[fi];
            mma3(acc[2 * l], acc[2 * l + 1], ah, al, Bh, Bl);
        }
    }
}

#define ZERO84(a) { _Pragma("unroll") for (int _i = 0; _i < 8; _i++) _Pragma("unroll") for (int _j = 0; _j < 4; _j++) (a)[_i][_j] = 0.f; }

__global__ void __launch_bounds__(THREADS, 1)
ac_mma_kernel(const float* __restrict__ obs, const float* __restrict__ hid,
              const float* __restrict__ enc_b, const float* __restrict__ b_ih,
              const float* __restrict__ b_hh, const float* __restrict__ v_b,
              const float* __restrict__ dec_b,
              float* __restrict__ out, float* __restrict__ hout_g) {
    extern __shared__ char sm[];
    const uint32_t sbase = smem_u32(sm);
    const int tid = threadIdx.x, lane = tid & 31, wid = tid >> 5;
    const int wm = wid & 3, wn = wid >> 2;
    const int row0 = blockIdx.x * 128;

    float* s_br   = (float*)(sm + OFF_BR);
    float* s_bz   = (float*)(sm + OFF_BZ);
    float* s_bin  = (float*)(sm + OFF_BIN);
    float* s_bhn  = (float*)(sm + OFF_BHN);
    float* s_encb = (float*)(sm + OFF_ENCB);
    float* s_vb   = (float*)(sm + OFF_VB);
    float* s_decb = (float*)(sm + OFF_DECB);

    if (tid < 128) {
        s_br[tid]   = b_ih[tid] + b_hh[tid];
        s_bz[tid]   = b_ih[128 + tid] + b_hh[128 + tid];
        s_bin[tid]  = b_ih[256 + tid];
        s_bhn[tid]  = b_hh[256 + tid];
        s_encb[tid] = enc_b[tid];
    }
    if (tid < 64) s_vb[tid]  = v_b[tid];
    if (tid < 16) s_decb[tid] = (tid < 10) ? dec_b[tid] : 0.f;

    // h -> bf16 splits (2 K blocks)
    conv_tile(hid, 128, 0,  row0, sm + OFF_H,         sm + OFF_H + 16384, tid);
    conv_tile(hid, 128, 64, row0, sm + OFF_H + 32768, sm + OFF_H + 49152, tid);

    const uint32_t xreg = sbase + OFF_X;
    const uint32_t hreg = sbase + OFF_H;
    const uint32_t oreg = sbase + OFF_OBS;

    // ======== enc GEMM: acc[2mt][8nt] = obs @ enc_w^T (K=256) ========
    float acc[2][8][4];
#pragma unroll
    for (int mi = 0; mi < 2; mi++) ZERO84(acc[mi]);

    const int kkp = (lane >> 4) << 3;
    for (int kb = 0; kb < 4; kb++) {
        __syncthreads();
        conv_tile(obs, 256, kb * 64, row0, sm + OFF_OBS, sm + OFF_OBS + 16384, tid);
        __syncthreads();
#pragma unroll
        for (int kt4 = 0; kt4 < 4; kt4++) {
            int ktg = kb * 4 + kt4;
            uint32_t ah[2][4], al[2][4];
#pragma unroll
            for (int mi = 0; mi < 2; mi++) {
                int arow = wm * 32 + mi * 16 + (lane & 15);
                uint32_t off = SWZ((uint32_t)(arow * 128 + (kt4 * 16 + kkp) * 2));
                ldm4(ah[mi], oreg + off);
                ldm4(al[mi], oreg + 16384 + off);
            }
#pragma unroll
            for (int l = 0; l < 4; l++) {
                int fi = ENC_F + ((wn * 4 + l) * 16 + ktg) * 32 + lane;
                uint4 Bh = g_bh[fi], Bl = g_bl[fi];
#pragma unroll
                for (int mi = 0; mi < 2; mi++)
                    mma3(acc[mi][2 * l], acc[mi][2 * l + 1], ah[mi], al[mi], Bh, Bl);
            }
        }
    }
    // enc epilogue: x = relu(acc + b) -> s_x splits
    {
        int rb = wm * 32 + (lane >> 2);
#pragma unroll
        for (int mi = 0; mi < 2; mi++)
#pragma unroll
            for (int ni = 0; ni < 8; ni++) {
                int col = wn * 64 + ni * 8 + (lane & 3) * 2;
                float b0 = s_encb[col], b1 = s_encb[col + 1];
#pragma unroll
                for (int rp = 0; rp < 2; rp++) {
                    int row = rb + mi * 16 + rp * 8;
                    float x0 = fmaxf(acc[mi][ni][rp * 2 + 0] + b0, 0.f);
                    float x1 = fmaxf(acc[mi][ni][rp * 2 + 1] + b1, 0.f);
                    store_pair_split(sm + OFF_X, row, col, x0, x1);
                }
            }
    }
    __syncthreads();

    // ======== GRU, two 64-row half-passes ========
    for (int hp = 0; hp < 2; hp++) {
        int mrow = hp * 64 + wm * 16;
        float rg[8][4], zg[8][4], an[8][4], hn[8][4];
        ZERO84(rg); ZERO84(zg); ZERO84(an); ZERO84(hn);
        gemm_gate(rg, xreg, mrow, wn, lane, WIHR_F);
        gemm_gate(rg, hreg, mrow, wn, lane, WHHR_F);
        gemm_gate(zg, xreg, mrow, wn, lane, WIHZ_F);
        gemm_gate(zg, hreg, mrow, wn, lane, WHHZ_F);
        gemm_gate(an, xreg, mrow, wn, lane, WIHN_F);
        gemm_gate(hn, hreg, mrow, wn, lane, WHHN_F);
        __syncthreads();   // all s_x/s_h reads of this half done before overwriting s_x

        int rb = mrow + (lane >> 2);
#pragma unroll
        for (int ni = 0; ni < 8; ni++) {
            int col = wn * 64 + ni * 8 + (lane & 3) * 2;
            float br0 = s_br[col],  br1 = s_br[col + 1];
            float bz0 = s_bz[col],  bz1 = s_bz[col + 1];
            float bi0 = s_bin[col], bi1 = s_bin[col + 1];
            float bh0 = s_bhn[col], bh1 = s_bhn[col + 1];
#pragma unroll
            for (int rp = 0; rp < 2; rp++) {
                int row = rb + rp * 8;
                uint32_t hoff = (uint32_t)((col >> 6) * 32768)
                              + SWZ((uint32_t)(row * 128 + (col & 63) * 2));
                uint32_t hhv = *(uint32_t*)(sm + OFF_H + hoff);
                uint32_t hlv = *(uint32_t*)(sm + OFF_H + 16384 + hoff);
                float h0 = bf_lo(hhv) + bf_lo(hlv);
                float h1 = bf_hi(hhv) + bf_hi(hlv);
                float r0 = sigm(rg[ni][rp * 2 + 0] + br0);
                float r1 = sigm(rg[ni][rp * 2 + 1] + br1);
                float z0 = sigm(zg[ni][rp * 2 + 0] + bz0);
                float z1 = sigm(zg[ni][rp * 2 + 1] + bz1);
                float n0 = tanhf(an[ni][rp * 2 + 0] + bi0 + r0 * (hn[ni][rp * 2 + 0] + bh0));
                float n1 = tanhf(an[ni][rp * 2 + 1] + bi1 + r1 * (hn[ni][rp * 2 + 1] + bh1));
                float o0 = (1.f - z0) * n0 + z0 * h0;
                float o1 = (1.f - z1) * n1 + z1 * h1;
                int grow = row0 + row;
                if (grow < SZ)
                    *(float2*)(hout_g + (size_t)grow * 128 + col) = make_float2(o0, o1);
                store_pair_split(sm + OFF_X, row, col, o0, o1);
            }
        }
        __syncthreads();
    }

    // ======== v GEMM: 128x64, A = h_out splits (s_x), K=128 ========
    float vc[2][4][4];
#pragma unroll
    for (int mi = 0; mi < 2; mi++)
#pragma unroll
        for (int ni = 0; ni < 4; ni++)
#pragma unroll
            for (int j = 0; j < 4; j++) vc[mi][ni][j] = 0.f;
#pragma unroll
    for (int kt = 0; kt < 8; kt++) {
        int kk = kt * 16 + kkp;
        uint32_t ah[2][4], al[2][4];
#pragma unroll
        for (int mi = 0; mi < 2; mi++) {
            int arow = wm * 32 + mi * 16 + (lane & 15);
            uint32_t off = (uint32_t)((kk >> 6) * 32768) + SWZ((uint32_t)(arow * 128 + (kk & 63) * 2));
            ldm4(ah[mi], xreg + off);
            ldm4(al[mi], xreg + 16384 + off);
        }
#pragma unroll
        for (int l = 0; l < 2; l++) {
            int fi = VW_F + ((wn * 2 + l) * 8 + kt) * 32 + lane;
            uint4 Bh = g_bh[fi], Bl = g_bl[fi];
#pragma unroll
            for (int mi = 0; mi < 2; mi++)
                mma3(vc[mi][2 * l], vc[mi][2 * l + 1], ah[mi], al[mi], Bh, Bl);
        }
    }
    // v epilogue -> splits into s_h block 0
    {
#pragma unroll
        for (int mi = 0; mi < 2; mi++)
#pragma unroll
            for (int ni = 0; ni < 4; ni++) {
                int col = wn * 32 + ni * 8 + (lane & 3) * 2;
                float b0 = s_vb[col], b1 = s_vb[col + 1];
#pragma unroll
                for (int rp = 0; rp < 2; rp++) {
                    int row = wm * 32 + mi * 16 + (lane >> 2) + rp * 8;
                    float v0 = fmaxf(vc[mi][ni][rp * 2 + 0] + b0, 0.f);
                    float v1 = fmaxf(vc[mi][ni][rp * 2 + 1] + b1, 0.f);
                    store_pair_split(sm + OFF_H, row, col, v0, v1);
                }
            }
    }
    __syncthreads();

    // ======== dec GEMM: [h_out | v] @ dec_w^T, K=192, N=16 ========
    float dc[2][4];
#pragma unroll
    for (int mi = 0; mi < 2; mi++)
#pragma unroll
        for (int j = 0; j < 4; j++) dc[mi][j] = 0.f;
#pragma unroll
    for (int kt = 0; kt < 12; kt++) {
        uint32_t areg2 = (kt < 8) ? xreg : hreg;
        int kk = ((kt < 8) ? kt : (kt - 8)) * 16 + kkp;
        uint32_t ah[2][4], al[2][4];
#pragma unroll
        for (int mi = 0; mi < 2; mi++) {
            int arow = wm * 32 + mi * 16 + (lane & 15);
            uint32_t off = (uint32_t)((kk >> 6) * 32768) + SWZ((uint32_t)(arow * 128 + (kk & 63) * 2));
            ldm4(ah[mi], areg2 + off);
            ldm4(al[mi], areg2 + 16384 + off);
        }
        int fi = DEC_F + kt * 32 + lane;
        uint4 Bh = g_bh[fi], Bl = g_bl[fi];
        uint32_t b0h = wn ? Bh.y : Bh.x, b1h = wn ? Bh.w : Bh.z;
        uint32_t b0l = wn ? Bl.y : Bl.x, b1l = wn ? Bl.w : Bl.z;
#pragma unroll
        for (int mi = 0; mi < 2; mi++) {
            mma_bf16(dc[mi], ah[mi], b0h, b1h);
            mma_bf16(dc[mi], ah[mi], b0l, b1l);
            mma_bf16(dc[mi], al[mi], b0h, b1h);
        }
    }
    // dec epilogue
    {
        int col = wn * 8 + (lane & 3) * 2;
        float b0 = s_decb[col], b1 = s_decb[col + 1];
#pragma unroll
        for (int mi = 0; mi < 2; mi++)
#pragma unroll
            for (int rp = 0; rp < 2; rp++) {
                int row = wm * 32 + mi * 16 + (lane >> 2) + rp * 8;
                int grow = row0 + row;
                if (grow < SZ) {
                    float o0 = dc[mi][rp * 2 + 0] + b0;
                    float o1 = dc[mi][rp * 2 + 1] + b1;
                    if (col < 10)     out[(size_t)grow * 10 + col] = o0;
                    if (col + 1 < 10) out[(size_t)grow * 10 + col + 1] = o1;
                }
            }
    }
}

extern "C" void kernel_launch(void* const* d_in, const int* in_sizes, int n_in,
                              void* d_out, int out_size) {
    const float* obs   = (const float*)d_in[0];
    const float* hid   = (const float*)d_in[1];
    const float* enc_w = (const float*)d_in[2];
    const float* enc_b = (const float*)d_in[3];
    const float* w_ih  = (const float*)d_in[4];
    const float* w_hh  = (const float*)d_in[5];
    const float* b_ih  = (const float*)d_in[6];
    const float* b_hh  = (const float*)d_in[7];
    const float* v_w   = (const float*)d_in[20];
    const float* v_b   = (const float*)d_in[21];
    const float* dec_w = (const float*)d_in[22];
    const float* dec_b = (const float*)d_in[23];

    float* out  = (float*)d_out;
    float* hout = out + (size_t)SZ * 10;

    prep_kernel<<<(FRAG_TOTAL + 255) / 256, 256>>>(enc_w, w_ih, w_hh, v_w, dec_w);

    cudaFuncSetAttribute(ac_mma_kernel, cudaFuncAttributeMaxDynamicSharedMemorySize, SMEM_TOTAL);
    ac_mma_kernel<<<GRID, THREADS, SMEM_TOTAL>>>(obs, hid, enc_b, b_ih, b_hh, v_b, dec_b, out, hout);
}

// round 5
// speedup vs baseline: 3.7559x; 1.3880x over previous
#include <cuda_runtime.h>
#include <cuda_fp16.h>
#include <math.h>
#include <stdint.h>

#define SZ 65535
#define THREADS 256
#define GRID 512

// ---- weight fragment image offsets (uint4 units) ----
#define ENC_F   0        // 8 n2 x 16 kt x 32
#define WIHR_F  4096     // 8 n2 x 8 kt x 32
#define WIHZ_F  6144
#define WIHN_F  8192
#define WHHR_F  10240
#define WHHZ_F  12288
#define WHHN_F  14336
#define VW_F    16384    // 4 n2 x 8 kt x 32
#define DEC_F   17408    // 1 n2 x 12 kt x 32
#define FRAG_TOTAL 17792

__device__ __align__(16) uint4 g_bh[FRAG_TOTAL];   // fp16 hi plane
__device__ __align__(16) uint4 g_bl[FRAG_TOTAL];   // fp16 lo plane

// ---- SMEM (bytes). Activations: fp16 single plane, 64-col K blocks (16KB each) ----
#define OFF_X    0        // 32KB: x (2 blocks), later h_out
#define OFF_H    32768    // 32KB: h (2 blocks); block0 later = v
#define OFF_OBS  65536    // 16KB: obs staging (1 block)
#define OFF_BR   81920
#define OFF_BZ   82432
#define OFF_BIN  82944
#define OFF_BHN  83456
#define OFF_ENCB 83968
#define OFF_VB   84480
#define OFF_DECB 84736
#define SMEM_TOTAL 84992

#define SWZ(o) ((o) ^ (((o) >> 3) & 0x70))

__device__ __forceinline__ uint32_t smem_u32(const void* p) {
    uint32_t a;
    asm("{ .reg .u64 t; cvta.to.shared.u64 t, %1; cvt.u32.u64 %0, t; }" : "=r"(a) : "l"(p));
    return a;
}

__device__ __forceinline__ void ldm4(uint32_t r[4], uint32_t a) {
    asm volatile("ldmatrix.sync.aligned.m8n8.x4.shared.b16 {%0,%1,%2,%3}, [%4];"
        : "=r"(r[0]), "=r"(r[1]), "=r"(r[2]), "=r"(r[3]) : "r"(a));
}

__device__ __forceinline__ void mma_f16(float c[4], const uint32_t a[4], uint32_t b0, uint32_t b1) {
    asm volatile("mma.sync.aligned.m16n8k16.row.col.f32.f16.f16.f32 "
        "{%0,%1,%2,%3}, {%4,%5,%6,%7}, {%8,%9}, {%0,%1,%2,%3};"
        : "+f"(c[0]), "+f"(c[1]), "+f"(c[2]), "+f"(c[3])
        : "r"(a[0]), "r"(a[1]), "r"(a[2]), "r"(a[3]), "r"(b0), "r"(b1));
}

__device__ __forceinline__ uint32_t packh2(float a, float b) {
    __half2 h = __floats2half2_rn(a, b);
    return *(uint32_t*)&h;
}
__device__ __forceinline__ uint32_t packh2_split(float a, float b, uint32_t& lo) {
    __half ah = __float2half_rn(a), bh = __float2half_rn(b);
    lo = packh2(a - __half2float(ah), b - __half2float(bh));
    return (uint32_t)__half_as_ushort(ah) | ((uint32_t)__half_as_ushort(bh) << 16);
}

__device__ __forceinline__ float sigm(float x) { return 1.f / (1.f + __expf(-x)); }

// store fp16 pair into activation region (blocked K layout)
__device__ __forceinline__ void store_pair(char* region, int row, int col, float a, float b) {
    uint32_t off = (uint32_t)((col >> 6) * 16384) + SWZ((uint32_t)(row * 128 + (col & 63) * 2));
    *(uint32_t*)(region + off) = packh2(a, b);
}

// [128 rows x 64 cols] fp32 gmem tile -> fp16 swizzled plane
__device__ void conv_tile(const float* __restrict__ g, int stride, int col0, int row0g,
                          char* dst, int tid) {
#pragma unroll
    for (int i = 0; i < 4; i++) {
        int t = tid + i * 256;
        int r = t >> 3, gi = t & 7;
        int gr = row0g + r;
        uint4 P;
        if (gr < SZ) {
            float4 a = *(const float4*)(g + (size_t)gr * stride + col0 + gi * 8);
            float4 b = *(const float4*)(g + (size_t)gr * stride + col0 + gi * 8 + 4);
            P.x = packh2(a.x, a.y); P.y = packh2(a.z, a.w);
            P.z = packh2(b.x, b.y); P.w = packh2(b.z, b.w);
        } else {
            P.x = P.y = P.z = P.w = 0u;
        }
        *(uint4*)(dst + SWZ((uint32_t)(r * 128 + gi * 16))) = P;
    }
}

// ---------------- prep: pack weights as fp16 hi/lo mma B-fragments ----------------
__global__ void prep_kernel(const float* __restrict__ enc_w, const float* __restrict__ w_ih,
                            const float* __restrict__ w_hh, const float* __restrict__ v_w,
                            const float* __restrict__ dec_w) {
    int idx = blockIdx.x * blockDim.x + threadIdx.x;
    if (idx >= FRAG_TOTAL) return;
    const float* W; int ldw, nmax, ktc, base;
    if (idx < 4096)       { W = enc_w; ldw = 256; nmax = 128; base = 0; ktc = 16; }
    else if (idx < 10240) { int g = (idx - 4096) / 2048; W = w_ih + (size_t)g * 128 * 128;
                            ldw = 128; nmax = 128; base = 4096 + g * 2048; ktc = 8; }
    else if (idx < 16384) { int g = (idx - 10240) / 2048; W = w_hh + (size_t)g * 128 * 128;
                            ldw = 128; nmax = 128; base = 10240 + g * 2048; ktc = 8; }
    else if (idx < 17408) { W = v_w; ldw = 128; nmax = 64; base = 16384; ktc = 8; }
    else                  { W = dec_w; ldw = 192; nmax = 10; base = 17408; ktc = 12; }

    int local = idx - base;
    int n2 = local / (ktc * 32);
    int rem = local - n2 * ktc * 32;
    int kt = rem >> 5, lane = rem & 31;
    int n = n2 * 16 + (lane >> 2);
    int k = kt * 16 + (lane & 3) * 2;

    float w[8];
#pragma unroll
    for (int dn = 0; dn < 2; dn++)
#pragma unroll
        for (int dk = 0; dk < 2; dk++)
#pragma unroll
            for (int e = 0; e < 2; e++) {
                int nn = n + dn * 8, kk = k + dk * 8 + e;
                w[(dn + dk * 2) * 2 + e] = (nn < nmax) ? W[(size_t)nn * ldw + kk] : 0.f;
            }
    uint4 H, L;
    H.x = packh2_split(w[0], w[1], L.x);
    H.y = packh2_split(w[2], w[3], L.y);
    H.z = packh2_split(w[4], w[5], L.z);
    H.w = packh2_split(w[6], w[7], L.w);
    g_bh[idx] = H;
    g_bl[idx] = L;
}

// one fused mma group: n16 pair, weights hi+lo
__device__ __forceinline__ void mma2(float cE[4], float cO[4], const uint32_t a[4],
                                     uint4 Bh, uint4 Bl) {
    mma_f16(cE, a, Bh.x, Bh.z);
    mma_f16(cE, a, Bl.x, Bl.z);
    mma_f16(cO, a, Bh.y, Bh.w);
    mma_f16(cO, a, Bl.y, Bl.w);
}

// GRU: one A-source feeding 3 gate accumulators (shared A fragments per kt)
__device__ __forceinline__ void gru_source(float (&A0)[8][4], float (&A1)[8][4], float (&A2)[8][4],
                                           uint32_t areg, int mrow, int wn, int lane,
                                           int fb0, int fb1, int fb2) {
    const int arow = mrow + (lane & 15);
    const int kkp = (lane >> 4) << 3;
#pragma unroll
    for (int kt = 0; kt < 8; kt++) {
        int kk = kt * 16 + kkp;
        uint32_t off = (uint32_t)((kk >> 6) * 16384) + SWZ((uint32_t)(arow * 128 + (kk & 63) * 2));
        uint32_t a[4];
        ldm4(a, areg + off);
#pragma unroll
        for (int l = 0; l < 4; l++) {
            int f0 = fb0 + ((wn * 4 + l) * 8 + kt) * 32 + lane;
            mma2(A0[2 * l], A0[2 * l + 1], a, g_bh[f0], g_bl[f0]);
        }
#pragma unroll
        for (int l = 0; l < 4; l++) {
            int f1 = fb1 + ((wn * 4 + l) * 8 + kt) * 32 + lane;
            mma2(A1[2 * l], A1[2 * l + 1], a, g_bh[f1], g_bl[f1]);
        }
#pragma unroll
        for (int l = 0; l < 4; l++) {
            int f2 = fb2 + ((wn * 4 + l) * 8 + kt) * 32 + lane;
            mma2(A2[2 * l], A2[2 * l + 1], a, g_bh[f2], g_bl[f2]);
        }
    }
}

#define ZERO84(a) { _Pragma("unroll") for (int _i = 0; _i < 8; _i++) _Pragma("unroll") for (int _j = 0; _j < 4; _j++) (a)[_i][_j] = 0.f; }

__global__ void __launch_bounds__(THREADS, 1)
ac_mma_kernel(const float* __restrict__ obs, const float* __restrict__ hid,
              const float* __restrict__ enc_b, const float* __restrict__ b_ih,
              const float* __restrict__ b_hh, const float* __restrict__ v_b,
              const float* __restrict__ dec_b,
              float* __restrict__ out, float* __restrict__ hout_g) {
    extern __shared__ char sm[];
    const uint32_t sbase = smem_u32(sm);
    const int tid = threadIdx.x, lane = tid & 31, wid = tid >> 5;
    const int wm = wid & 3, wn = wid >> 2;
    const int row0 = blockIdx.x * 128;

    float* s_br   = (float*)(sm + OFF_BR);
    float* s_bz   = (float*)(sm + OFF_BZ);
    float* s_bin  = (float*)(sm + OFF_BIN);
    float* s_bhn  = (float*)(sm + OFF_BHN);
    float* s_encb = (float*)(sm + OFF_ENCB);
    float* s_vb   = (float*)(sm + OFF_VB);
    float* s_decb = (float*)(sm + OFF_DECB);

    if (tid < 128) {
        s_br[tid]   = b_ih[tid] + b_hh[tid];
        s_bz[tid]   = b_ih[128 + tid] + b_hh[128 + tid];
        s_bin[tid]  = b_ih[256 + tid];
        s_bhn[tid]  = b_hh[256 + tid];
        s_encb[tid] = enc_b[tid];
    }
    if (tid < 64) s_vb[tid]   = v_b[tid];
    if (tid < 16) s_decb[tid] = (tid < 10) ? dec_b[tid] : 0.f;

    // h -> fp16 plane (2 K blocks)
    conv_tile(hid, 128, 0,  row0, sm + OFF_H,         tid);
    conv_tile(hid, 128, 64, row0, sm + OFF_H + 16384, tid);

    const uint32_t xreg = sbase + OFF_X;
    const uint32_t hreg = sbase + OFF_H;
    const uint32_t oreg = sbase + OFF_OBS;
    const int kkp = (lane >> 4) << 3;

    // ======== enc GEMM: obs @ enc_w^T (K=256) ========
    float acc[2][8][4];
#pragma unroll
    for (int mi = 0; mi < 2; mi++) ZERO84(acc[mi]);

    for (int kb = 0; kb < 4; kb++) {
        __syncthreads();
        conv_tile(obs, 256, kb * 64, row0, sm + OFF_OBS, tid);
        __syncthreads();
#pragma unroll
        for (int kt4 = 0; kt4 < 4; kt4++) {
            int ktg = kb * 4 + kt4;
            uint32_t a[2][4];
#pragma unroll
            for (int mi = 0; mi < 2; mi++) {
                int arow = wm * 32 + mi * 16 + (lane & 15);
                ldm4(a[mi], oreg + SWZ((uint32_t)(arow * 128 + (kt4 * 16 + kkp) * 2)));
            }
#pragma unroll
            for (int l = 0; l < 4; l++) {
                int fi = ENC_F + ((wn * 4 + l) * 16 + ktg) * 32 + lane;
                uint4 Bh = g_bh[fi], Bl = g_bl[fi];
#pragma unroll
                for (int mi = 0; mi < 2; mi++)
                    mma2(acc[mi][2 * l], acc[mi][2 * l + 1], a[mi], Bh, Bl);
            }
        }
    }
    // enc epilogue: x = relu(acc + b) -> s_x
    {
        int rb = wm * 32 + (lane >> 2);
#pragma unroll
        for (int mi = 0; mi < 2; mi++)
#pragma unroll
            for (int ni = 0; ni < 8; ni++) {
                int col = wn * 64 + ni * 8 + (lane & 3) * 2;
                float b0 = s_encb[col], b1 = s_encb[col + 1];
#pragma unroll
                for (int rp = 0; rp < 2; rp++) {
                    int row = rb + mi * 16 + rp * 8;
                    store_pair(sm + OFF_X, row, col,
                               fmaxf(acc[mi][ni][rp * 2 + 0] + b0, 0.f),
                               fmaxf(acc[mi][ni][rp * 2 + 1] + b1, 0.f));
                }
            }
    }
    __syncthreads();

    // ======== GRU, two 64-row half-passes ========
    for (int hp = 0; hp < 2; hp++) {
        int mrow = hp * 64 + wm * 16;
        float rg[8][4], zg[8][4], an[8][4], hn[8][4];
        ZERO84(rg); ZERO84(zg); ZERO84(an); ZERO84(hn);
        gru_source(rg, zg, an, xreg, mrow, wn, lane, WIHR_F, WIHZ_F, WIHN_F);
        gru_source(rg, zg, hn, hreg, mrow, wn, lane, WHHR_F, WHHZ_F, WHHN_F);
        __syncthreads();   // all reads of this half done before overwriting s_x

        int rb = mrow + (lane >> 2);
#pragma unroll
        for (int ni = 0; ni < 8; ni++) {
            int col = wn * 64 + ni * 8 + (lane & 3) * 2;
            float br0 = s_br[col],  br1 = s_br[col + 1];
            float bz0 = s_bz[col],  bz1 = s_bz[col + 1];
            float bi0 = s_bin[col], bi1 = s_bin[col + 1];
            float bh0 = s_bhn[col], bh1 = s_bhn[col + 1];
#pragma unroll
            for (int rp = 0; rp < 2; rp++) {
                int row = rb + rp * 8;
                int grow = row0 + row;
                float h0 = 0.f, h1 = 0.f;
                if (grow < SZ) {
                    float2 t = *(const float2*)(hid + (size_t)grow * 128 + col);
                    h0 = t.x; h1 = t.y;
                }
                float r0 = sigm(rg[ni][rp * 2 + 0] + br0);
                float r1 = sigm(rg[ni][rp * 2 + 1] + br1);
                float z0 = sigm(zg[ni][rp * 2 + 0] + bz0);
                float z1 = sigm(zg[ni][rp * 2 + 1] + bz1);
                float n0 = tanhf(an[ni][rp * 2 + 0] + bi0 + r0 * (hn[ni][rp * 2 + 0] + bh0));
                float n1 = tanhf(an[ni][rp * 2 + 1] + bi1 + r1 * (hn[ni][rp * 2 + 1] + bh1));
                float o0 = (1.f - z0) * n0 + z0 * h0;
                float o1 = (1.f - z1) * n1 + z1 * h1;
                if (grow < SZ)
                    *(float2*)(hout_g + (size_t)grow * 128 + col) = make_float2(o0, o1);
                store_pair(sm + OFF_X, row, col, o0, o1);
            }
        }
        __syncthreads();
    }

    // ======== v GEMM: 128x64, A = h_out (s_x), K=128 ========
    float vc[2][4][4];
#pragma unroll
    for (int mi = 0; mi < 2; mi++)
#pragma unroll
        for (int ni = 0; ni < 4; ni++)
#pragma unroll
            for (int j = 0; j < 4; j++) vc[mi][ni][j] = 0.f;
#pragma unroll
    for (int kt = 0; kt < 8; kt++) {
        int kk = kt * 16 + kkp;
        uint32_t a[2][4];
#pragma unroll
        for (int mi = 0; mi < 2; mi++) {
            int arow = wm * 32 + mi * 16 + (lane & 15);
            ldm4(a[mi], xreg + (uint32_t)((kk >> 6) * 16384) + SWZ((uint32_t)(arow * 128 + (kk & 63) * 2)));
        }
#pragma unroll
        for (int l = 0; l < 2; l++) {
            int fi = VW_F + ((wn * 2 + l) * 8 + kt) * 32 + lane;
            uint4 Bh = g_bh[fi], Bl = g_bl[fi];
#pragma unroll
            for (int mi = 0; mi < 2; mi++)
                mma2(vc[mi][2 * l], vc[mi][2 * l + 1], a[mi], Bh, Bl);
        }
    }
    // v epilogue -> s_h block 0
    {
#pragma unroll
        for (int mi = 0; mi < 2; mi++)
#pragma unroll
            for (int ni = 0; ni < 4; ni++) {
                int col = wn * 32 + ni * 8 + (lane & 3) * 2;
                float b0 = s_vb[col], b1 = s_vb[col + 1];
#pragma unroll
                for (int rp = 0; rp < 2; rp++) {
                    int row = wm * 32 + mi * 16 + (lane >> 2) + rp * 8;
                    store_pair(sm + OFF_H, row, col,
                               fmaxf(vc[mi][ni][rp * 2 + 0] + b0, 0.f),
                               fmaxf(vc[mi][ni][rp * 2 + 1] + b1, 0.f));
                }
            }
    }
    __syncthreads();

    // ======== dec GEMM: [h_out | v] @ dec_w^T, K=192, N=16 ========
    float dc[2][4];
#pragma unroll
    for (int mi = 0; mi < 2; mi++)
#pragma unroll
        for (int j = 0; j < 4; j++) dc[mi][j] = 0.f;
#pragma unroll
    for (int kt = 0; kt < 12; kt++) {
        uint32_t areg2 = (kt < 8) ? xreg : hreg;
        int kk = ((kt < 8) ? kt : (kt - 8)) * 16 + kkp;
        uint32_t a[2][4];
#pragma unroll
        for (int mi = 0; mi < 2; mi++) {
            int arow = wm * 32 + mi * 16 + (lane & 15);
            ldm4(a[mi], areg2 + (uint32_t)((kk >> 6) * 16384) + SWZ((uint32_t)(arow * 128 + (kk & 63) * 2)));
        }
        int fi = DEC_F + kt * 32 + lane;
        uint4 Bh = g_bh[fi], Bl = g_bl[fi];
        uint32_t b0h = wn ? Bh.y : Bh.x, b1h = wn ? Bh.w : Bh.z;
        uint32_t b0l = wn ? Bl.y : Bl.x, b1l = wn ? Bl.w : Bl.z;
#pragma unroll
        for (int mi = 0; mi < 2; mi++) {
            mma_f16(dc[mi], a[mi], b0h, b1h);
            mma_f16(dc[mi], a[mi], b0l, b1l);
        }
    }
    // dec epilogue
    {
        int col = wn * 8 + (lane & 3) * 2;
        float b0 = s_decb[col], b1 = s_decb[col + 1];
#pragma unroll
        for (int mi = 0; mi < 2; mi++)
#pragma unroll
            for (int rp = 0; rp < 2; rp++) {
                int row = wm * 32 + mi * 16 + (lane >> 2) + rp * 8;
                int grow = row0 + row;
                if (grow < SZ) {
                    float o0 = dc[mi][rp * 2 + 0] + b0;
                    float o1 = dc[mi][rp * 2 + 1] + b1;
                    if (col < 10)     out[(size_t)grow * 10 + col] = o0;
                    if (col + 1 < 10) out[(size_t)grow * 10 + col + 1] = o1;
                }
            }
    }
}

extern "C" void kernel_launch(void* const* d_in, const int* in_sizes, int n_in,
                              void* d_out, int out_size) {
    const float* obs   = (const float*)d_in[0];
    const float* hid   = (const float*)d_in[1];
    const float* enc_w = (const float*)d_in[2];
    const float* enc_b = (const float*)d_in[3];
    const float* w_ih  = (const float*)d_in[4];
    const float* w_hh  = (const float*)d_in[5];
    const float* b_ih  = (const float*)d_in[6];
    const float* b_hh  = (const float*)d_in[7];
    const float* v_w   = (const float*)d_in[20];
    const float* v_b   = (const float*)d_in[21];
    const float* dec_w = (const float*)d_in[22];
    const float* dec_b = (const float*)d_in[23];

    float* out  = (float*)d_out;
    float* hout = out + (size_t)SZ * 10;

    prep_kernel<<<(FRAG_TOTAL + 255) / 256, 256>>>(enc_w, w_ih, w_hh, v_w, dec_w);

    cudaFuncSetAttribute(ac_mma_kernel, cudaFuncAttributeMaxDynamicSharedMemorySize, SMEM_TOTAL);
    ac_mma_kernel<<<GRID, THREADS, SMEM_TOTAL>>>(obs, hid, enc_b, b_ih, b_hh, v_b, dec_b, out, hout);
}

// round 6
// speedup vs baseline: 4.1929x; 1.1164x over previous
#include <cuda_runtime.h>
#include <cuda_fp16.h>
#include <math.h>
#include <stdint.h>

#define SZ 65535
#define THREADS 256
#define GRID 512

// ---- weight fragment image offsets (uint4 units) ----
#define ENC_F   0        // 8 n2 x 16 kt x 32
#define WIHR_F  4096     // 8 n2 x 8 kt x 32
#define WIHZ_F  6144
#define WIHN_F  8192
#define WHHR_F  10240
#define WHHZ_F  12288
#define WHHN_F  14336
#define VW_F    16384    // 4 n2 x 8 kt x 32
#define DEC_F   17408    // 1 n2 x 12 kt x 32
#define FRAG_TOTAL 17792

__device__ __align__(16) uint4 g_bh[FRAG_TOTAL];   // fp16 hi plane
__device__ __align__(16) uint4 g_bl[FRAG_TOTAL];   // fp16 lo plane

// ---- SMEM (bytes) ----
#define OFF_X    0        // 32KB: x (2 K blocks), later h_out
#define OFF_H    32768    // 32KB: h (2 K blocks); block0 later = v
#define OFF_OBS  65536    // 16KB: obs staging (enc phase only)
#define OFF_RZ   65536    // 33KB: packed sigma(r),sigma(z) fp16 (GRU phase, overlaps obs)
#define OFF_BR   99328
#define OFF_BZ   99840
#define OFF_BIN  100352
#define OFF_BHN  100864
#define OFF_ENCB 101376
#define OFF_VB   101888
#define OFF_DECB 102144
#define SMEM_TOTAL 102400

#define SWZ(o) ((o) ^ (((o) >> 3) & 0x70))
// rz stash: row-local 0..63, c2 0..63; stride 66 uint2 to spread banks
#define RZ_OFF(row, c2) ((uint32_t)(OFF_RZ + (((row) * 66 + (c2)) << 3)))

__device__ __forceinline__ uint32_t smem_u32(const void* p) {
    uint32_t a;
    asm("{ .reg .u64 t; cvta.to.shared.u64 t, %1; cvt.u32.u64 %0, t; }" : "=r"(a) : "l"(p));
    return a;
}

__device__ __forceinline__ void ldm4(uint32_t r[4], uint32_t a) {
    asm volatile("ldmatrix.sync.aligned.m8n8.x4.shared.b16 {%0,%1,%2,%3}, [%4];"
        : "=r"(r[0]), "=r"(r[1]), "=r"(r[2]), "=r"(r[3]) : "r"(a));
}

__device__ __forceinline__ void mma_f16(float c[4], const uint32_t a[4], uint32_t b0, uint32_t b1) {
    asm volatile("mma.sync.aligned.m16n8k16.row.col.f32.f16.f16.f32 "
        "{%0,%1,%2,%3}, {%4,%5,%6,%7}, {%8,%9}, {%0,%1,%2,%3};"
        : "+f"(c[0]), "+f"(c[1]), "+f"(c[2]), "+f"(c[3])
        : "r"(a[0]), "r"(a[1]), "r"(a[2]), "r"(a[3]), "r"(b0), "r"(b1));
}

__device__ __forceinline__ uint32_t packh2(float a, float b) {
    __half2 h = __floats2half2_rn(a, b);
    return *(uint32_t*)&h;
}
__device__ __forceinline__ uint32_t packh2_split(float a, float b, uint32_t& lo) {
    __half ah = __float2half_rn(a), bh = __float2half_rn(b);
    lo = packh2(a - __half2float(ah), b - __half2float(bh));
    return (uint32_t)__half_as_ushort(ah) | ((uint32_t)__half_as_ushort(bh) << 16);
}
__device__ __forceinline__ float h_lo(uint32_t v) {
    return __half2float(__ushort_as_half((unsigned short)(v & 0xFFFF)));
}
__device__ __forceinline__ float h_hi(uint32_t v) {
    return __half2float(__ushort_as_half((unsigned short)(v >> 16)));
}

__device__ __forceinline__ float sigm(float x) { return 1.f / (1.f + __expf(-x)); }

__device__ __forceinline__ void store_pair(char* region, int row, int col, float a, float b) {
    uint32_t off = (uint32_t)((col >> 6) * 16384) + SWZ((uint32_t)(row * 128 + (col & 63) * 2));
    *(uint32_t*)(region + off) = packh2(a, b);
}

// [128 rows x 64 cols] fp32 gmem tile -> fp16 swizzled plane
__device__ void conv_tile(const float* __restrict__ g, int stride, int col0, int row0g,
                          char* dst, int tid) {
#pragma unroll
    for (int i = 0; i < 4; i++) {
        int t = tid + i * 256;
        int r = t >> 3, gi = t & 7;
        int gr = row0g + r;
        uint4 P;
        if (gr < SZ) {
            float4 a = *(const float4*)(g + (size_t)gr * stride + col0 + gi * 8);
            float4 b = *(const float4*)(g + (size_t)gr * stride + col0 + gi * 8 + 4);
            P.x = packh2(a.x, a.y); P.y = packh2(a.z, a.w);
            P.z = packh2(b.x, b.y); P.w = packh2(b.z, b.w);
        } else {
            P.x = P.y = P.z = P.w = 0u;
        }
        *(uint4*)(dst + SWZ((uint32_t)(r * 128 + gi * 16))) = P;
    }
}

// ---------------- prep: pack weights as fp16 hi/lo mma B-fragments ----------------
__global__ void prep_kernel(const float* __restrict__ enc_w, const float* __restrict__ w_ih,
                            const float* __restrict__ w_hh, const float* __restrict__ v_w,
                            const float* __restrict__ dec_w) {
    int idx = blockIdx.x * blockDim.x + threadIdx.x;
    if (idx >= FRAG_TOTAL) return;
    const float* W; int ldw, nmax, ktc, base;
    if (idx < 4096)       { W = enc_w; ldw = 256; nmax = 128; base = 0; ktc = 16; }
    else if (idx < 10240) { int g = (idx - 4096) / 2048; W = w_ih + (size_t)g * 128 * 128;
                            ldw = 128; nmax = 128; base = 4096 + g * 2048; ktc = 8; }
    else if (idx < 16384) { int g = (idx - 10240) / 2048; W = w_hh + (size_t)g * 128 * 128;
                            ldw = 128; nmax = 128; base = 10240 + g * 2048; ktc = 8; }
    else if (idx < 17408) { W = v_w; ldw = 128; nmax = 64; base = 16384; ktc = 8; }
    else                  { W = dec_w; ldw = 192; nmax = 10; base = 17408; ktc = 12; }

    int local = idx - base;
    int n2 = local / (ktc * 32);
    int rem = local - n2 * ktc * 32;
    int kt = rem >> 5, lane = rem & 31;
    int n = n2 * 16 + (lane >> 2);
    int k = kt * 16 + (lane & 3) * 2;

    float w[8];
#pragma unroll
    for (int dn = 0; dn < 2; dn++)
#pragma unroll
        for (int dk = 0; dk < 2; dk++)
#pragma unroll
            for (int e = 0; e < 2; e++) {
                int nn = n + dn * 8, kk = k + dk * 8 + e;
                w[(dn + dk * 2) * 2 + e] = (nn < nmax) ? W[(size_t)nn * ldw + kk] : 0.f;
            }
    uint4 H, L;
    H.x = packh2_split(w[0], w[1], L.x);
    H.y = packh2_split(w[2], w[3], L.y);
    H.z = packh2_split(w[4], w[5], L.z);
    H.w = packh2_split(w[6], w[7], L.w);
    g_bh[idx] = H;
    g_bl[idx] = L;
}

__device__ __forceinline__ void mma2(float cE[4], float cO[4], const uint32_t a[4],
                                     uint4 Bh, uint4 Bl) {
    mma_f16(cE, a, Bh.x, Bh.z);
    mma_f16(cE, a, Bl.x, Bl.z);
    mma_f16(cO, a, Bh.y, Bh.w);
    mma_f16(cO, a, Bl.y, Bl.w);
}

// one A-source feeding TWO gate accumulators
__device__ __forceinline__ void gru_pass2(float (&A0)[8][4], float (&A1)[8][4],
                                          uint32_t areg, int mrow, int wn, int lane,
                                          int fb0, int fb1) {
    const int arow = mrow + (lane & 15);
    const int kkp = (lane >> 4) << 3;
#pragma unroll
    for (int kt = 0; kt < 8; kt++) {
        int kk = kt * 16 + kkp;
        uint32_t a[4];
        ldm4(a, areg + (uint32_t)((kk >> 6) * 16384) + SWZ((uint32_t)(arow * 128 + (kk & 63) * 2)));
#pragma unroll
        for (int l = 0; l < 4; l++) {
            int f0 = fb0 + ((wn * 4 + l) * 8 + kt) * 32 + lane;
            mma2(A0[2 * l], A0[2 * l + 1], a, g_bh[f0], g_bl[f0]);
        }
#pragma unroll
        for (int l = 0; l < 4; l++) {
            int f1 = fb1 + ((wn * 4 + l) * 8 + kt) * 32 + lane;
            mma2(A1[2 * l], A1[2 * l + 1], a, g_bh[f1], g_bl[f1]);
        }
    }
}

// one A-source feeding ONE gate accumulator
__device__ __forceinline__ void gru_pass1(float (&A0)[8][4],
                                          uint32_t areg, int mrow, int wn, int lane, int fb0) {
    const int arow = mrow + (lane & 15);
    const int kkp = (lane >> 4) << 3;
#pragma unroll
    for (int kt = 0; kt < 8; kt++) {
        int kk = kt * 16 + kkp;
        uint32_t a[4];
        ldm4(a, areg + (uint32_t)((kk >> 6) * 16384) + SWZ((uint32_t)(arow * 128 + (kk & 63) * 2)));
#pragma unroll
        for (int l = 0; l < 4; l++) {
            int f0 = fb0 + ((wn * 4 + l) * 8 + kt) * 32 + lane;
            mma2(A0[2 * l], A0[2 * l + 1], a, g_bh[f0], g_bl[f0]);
        }
    }
}

#define ZERO84(a) { _Pragma("unroll") for (int _i = 0; _i < 8; _i++) _Pragma("unroll") for (int _j = 0; _j < 4; _j++) (a)[_i][_j] = 0.f; }

__global__ void __launch_bounds__(THREADS, 2)
ac_mma_kernel(const float* __restrict__ obs, const float* __restrict__ hid,
              const float* __restrict__ enc_b, const float* __restrict__ b_ih,
              const float* __restrict__ b_hh, const float* __restrict__ v_b,
              const float* __restrict__ dec_b,
              float* __restrict__ out, float* __restrict__ hout_g) {
    extern __shared__ char sm[];
    const uint32_t sbase = smem_u32(sm);
    const int tid = threadIdx.x, lane = tid & 31, wid = tid >> 5;
    const int wm = wid & 3, wn = wid >> 2;
    const int row0 = blockIdx.x * 128;

    float* s_br   = (float*)(sm + OFF_BR);
    float* s_bz   = (float*)(sm + OFF_BZ);
    float* s_bin  = (float*)(sm + OFF_BIN);
    float* s_bhn  = (float*)(sm + OFF_BHN);
    float* s_encb = (float*)(sm + OFF_ENCB);
    float* s_vb   = (float*)(sm + OFF_VB);
    float* s_decb = (float*)(sm + OFF_DECB);

    if (tid < 128) {
        s_br[tid]   = b_ih[tid] + b_hh[tid];
        s_bz[tid]   = b_ih[128 + tid] + b_hh[128 + tid];
        s_bin[tid]  = b_ih[256 + tid];
        s_bhn[tid]  = b_hh[256 + tid];
        s_encb[tid] = enc_b[tid];
    }
    if (tid < 64) s_vb[tid]   = v_b[tid];
    if (tid < 16) s_decb[tid] = (tid < 10) ? dec_b[tid] : 0.f;

    // h -> fp16 plane (2 K blocks)
    conv_tile(hid, 128, 0,  row0, sm + OFF_H,         tid);
    conv_tile(hid, 128, 64, row0, sm + OFF_H + 16384, tid);

    const uint32_t xreg = sbase + OFF_X;
    const uint32_t hreg = sbase + OFF_H;
    const uint32_t oreg = sbase + OFF_OBS;
    const int kkp = (lane >> 4) << 3;

    // ======== enc GEMM: obs @ enc_w^T (K=256) ========
    {
        float acc[2][8][4];
#pragma unroll
        for (int mi = 0; mi < 2; mi++) ZERO84(acc[mi]);

        for (int kb = 0; kb < 4; kb++) {
            __syncthreads();
            conv_tile(obs, 256, kb * 64, row0, sm + OFF_OBS, tid);
            __syncthreads();
#pragma unroll
            for (int kt4 = 0; kt4 < 4; kt4++) {
                int ktg = kb * 4 + kt4;
                uint32_t a[2][4];
#pragma unroll
                for (int mi = 0; mi < 2; mi++) {
                    int arow = wm * 32 + mi * 16 + (lane & 15);
                    ldm4(a[mi], oreg + SWZ((uint32_t)(arow * 128 + (kt4 * 16 + kkp) * 2)));
                }
#pragma unroll
                for (int l = 0; l < 4; l++) {
                    int fi = ENC_F + ((wn * 4 + l) * 16 + ktg) * 32 + lane;
                    uint4 Bh = g_bh[fi], Bl = g_bl[fi];
#pragma unroll
                    for (int mi = 0; mi < 2; mi++)
                        mma2(acc[mi][2 * l], acc[mi][2 * l + 1], a[mi], Bh, Bl);
                }
            }
        }
        // x = relu(acc + b) -> s_x
        int rb = wm * 32 + (lane >> 2);
#pragma unroll
        for (int mi = 0; mi < 2; mi++)
#pragma unroll
            for (int ni = 0; ni < 8; ni++) {
                int col = wn * 64 + ni * 8 + (lane & 3) * 2;
                float b0 = s_encb[col], b1 = s_encb[col + 1];
#pragma unroll
                for (int rp = 0; rp < 2; rp++) {
                    int row = rb + mi * 16 + rp * 8;
                    store_pair(sm + OFF_X, row, col,
                               fmaxf(acc[mi][ni][rp * 2 + 0] + b0, 0.f),
                               fmaxf(acc[mi][ni][rp * 2 + 1] + b1, 0.f));
                }
            }
    }
    __syncthreads();

    // ======== GRU, two 64-row halves, each as (r,z) pass then (n) pass ========
    for (int hp = 0; hp < 2; hp++) {
        int mrow = hp * 64 + wm * 16;

        // ---- pass A: r,z ----
        {
            float rg[8][4], zg[8][4];
            ZERO84(rg); ZERO84(zg);
            gru_pass2(rg, zg, xreg, mrow, wn, lane, WIHR_F, WIHZ_F);
            gru_pass2(rg, zg, hreg, mrow, wn, lane, WHHR_F, WHHZ_F);
            // sigma + stash fp16 (warp-local footprint; no sync needed)
            int rbl = wm * 16 + (lane >> 2);   // local row in half
#pragma unroll
            for (int ni = 0; ni < 8; ni++) {
                int col = wn * 64 + ni * 8 + (lane & 3) * 2;
                int c2 = col >> 1;
                float br0 = s_br[col], br1 = s_br[col + 1];
                float bz0 = s_bz[col], bz1 = s_bz[col + 1];
#pragma unroll
                for (int rp = 0; rp < 2; rp++) {
                    int rl = rbl + rp * 8;
                    uint2 p;
                    p.x = packh2(sigm(rg[ni][rp * 2 + 0] + br0), sigm(rg[ni][rp * 2 + 1] + br1));
                    p.y = packh2(sigm(zg[ni][rp * 2 + 0] + bz0), sigm(zg[ni][rp * 2 + 1] + bz1));
                    *(uint2*)(sm + RZ_OFF(rl, c2)) = p;
                }
            }
        }

        // ---- pass B: a_n (from x), h_n (from h) ----
        {
            float an[8][4], hn[8][4];
            ZERO84(an); ZERO84(hn);
            gru_pass1(an, xreg, mrow, wn, lane, WIHN_F);
            gru_pass1(hn, hreg, mrow, wn, lane, WHHN_F);
            __syncthreads();   // all s_x reads of this half done before epilogue overwrites

            int rbl = wm * 16 + (lane >> 2);
#pragma unroll
            for (int ni = 0; ni < 8; ni++) {
                int col = wn * 64 + ni * 8 + (lane & 3) * 2;
                int c2 = col >> 1;
                float bi0 = s_bin[col], bi1 = s_bin[col + 1];
                float bh0 = s_bhn[col], bh1 = s_bhn[col + 1];
#pragma unroll
                for (int rp = 0; rp < 2; rp++) {
                    int rl = rbl + rp * 8;
                    int row = hp * 64 + rl;
                    int grow = row0 + row;
                    float h0 = 0.f, h1 = 0.f;
                    if (grow < SZ) {
                        float2 t = *(const float2*)(hid + (size_t)grow * 128 + col);
                        h0 = t.x; h1 = t.y;
                    }
                    uint2 p = *(const uint2*)(sm + RZ_OFF(rl, c2));
                    float r0 = h_lo(p.x), r1 = h_hi(p.x);
                    float z0 = h_lo(p.y), z1 = h_hi(p.y);
                    float n0 = tanhf(an[ni][rp * 2 + 0] + bi0 + r0 * (hn[ni][rp * 2 + 0] + bh0));
                    float n1 = tanhf(an[ni][rp * 2 + 1] + bi1 + r1 * (hn[ni][rp * 2 + 1] + bh1));
                    float o0 = (1.f - z0) * n0 + z0 * h0;
                    float o1 = (1.f - z1) * n1 + z1 * h1;
                    if (grow < SZ)
                        *(float2*)(hout_g + (size_t)grow * 128 + col) = make_float2(o0, o1);
                    store_pair(sm + OFF_X, row, col, o0, o1);
                }
            }
        }
        __syncthreads();
    }

    // ======== v GEMM: 128x64, A = h_out (s_x), K=128 ========
    {
        float vc[2][4][4];
#pragma unroll
        for (int mi = 0; mi < 2; mi++)
#pragma unroll
            for (int ni = 0; ni < 4; ni++)
#pragma unroll
                for (int j = 0; j < 4; j++) vc[mi][ni][j] = 0.f;
#pragma unroll
        for (int kt = 0; kt < 8; kt++) {
            int kk = kt * 16 + kkp;
            uint32_t a[2][4];
#pragma unroll
            for (int mi = 0; mi < 2; mi++) {
                int arow = wm * 32 + mi * 16 + (lane & 15);
                ldm4(a[mi], xreg + (uint32_t)((kk >> 6) * 16384) + SWZ((uint32_t)(arow * 128 + (kk & 63) * 2)));
            }
#pragma unroll
            for (int l = 0; l < 2; l++) {
                int fi = VW_F + ((wn * 2 + l) * 8 + kt) * 32 + lane;
                uint4 Bh = g_bh[fi], Bl = g_bl[fi];
#pragma unroll
                for (int mi = 0; mi < 2; mi++)
                    mma2(vc[mi][2 * l], vc[mi][2 * l + 1], a[mi], Bh, Bl);
            }
        }
        // v -> s_h block 0
#pragma unroll
        for (int mi = 0; mi < 2; mi++)
#pragma unroll
            for (int ni = 0; ni < 4; ni++) {
                int col = wn * 32 + ni * 8 + (lane & 3) * 2;
                float b0 = s_vb[col], b1 = s_vb[col + 1];
#pragma unroll
                for (int rp = 0; rp < 2; rp++) {
                    int row = wm * 32 + mi * 16 + (lane >> 2) + rp * 8;
                    store_pair(sm + OFF_H, row, col,
                               fmaxf(vc[mi][ni][rp * 2 + 0] + b0, 0.f),
                               fmaxf(vc[mi][ni][rp * 2 + 1] + b1, 0.f));
                }
            }
    }
    __syncthreads();

    // ======== dec GEMM: [h_out | v] @ dec_w^T, K=192, N=16 ========
    {
        float dc[2][4];
#pragma unroll
        for (int mi = 0; mi < 2; mi++)
#pragma unroll
            for (int j = 0; j < 4; j++) dc[mi][j] = 0.f;
#pragma unroll
        for (int kt = 0; kt < 12; kt++) {
            uint32_t areg2 = (kt < 8) ? xreg : hreg;
            int kk = ((kt < 8) ? kt : (kt - 8)) * 16 + kkp;
            uint32_t a[2][4];
#pragma unroll
            for (int mi = 0; mi < 2; mi++) {
                int arow = wm * 32 + mi * 16 + (lane & 15);
                ldm4(a[mi], areg2 + (uint32_t)((kk >> 6) * 16384) + SWZ((uint32_t)(arow * 128 + (kk & 63) * 2)));
            }
            int fi = DEC_F + kt * 32 + lane;
            uint4 Bh = g_bh[fi], Bl = g_bl[fi];
            uint32_t b0h = wn ? Bh.y : Bh.x, b1h = wn ? Bh.w : Bh.z;
            uint32_t b0l = wn ? Bl.y : Bl.x, b1l = wn ? Bl.w : Bl.z;
#pragma unroll
            for (int mi = 0; mi < 2; mi++) {
                mma_f16(dc[mi], a[mi], b0h, b1h);
                mma_f16(dc[mi], a[mi], b0l, b1l);
            }
        }
        int col = wn * 8 + (lane & 3) * 2;
        float b0 = s_decb[col], b1 = s_decb[col + 1];
#pragma unroll
        for (int mi = 0; mi < 2; mi++)
#pragma unroll
            for (int rp = 0; rp < 2; rp++) {
                int row = wm * 32 + mi * 16 + (lane >> 2) + rp * 8;
                int grow = row0 + row;
                if (grow < SZ) {
                    float o0 = dc[mi][rp * 2 + 0] + b0;
                    float o1 = dc[mi][rp * 2 + 1] + b1;
                    if (col < 10)     out[(size_t)grow * 10 + col] = o0;
                    if (col + 1 < 10) out[(size_t)grow * 10 + col + 1] = o1;
                }
            }
    }
}

extern "C" void kernel_launch(void* const* d_in, const int* in_sizes, int n_in,
                              void* d_out, int out_size) {
    const float* obs   = (const float*)d_in[0];
    const float* hid   = (const float*)d_in[1];
    const float* enc_w = (const float*)d_in[2];
    const float* enc_b = (const float*)d_in[3];
    const float* w_ih  = (const float*)d_in[4];
    const float* w_hh  = (const float*)d_in[5];
    const float* b_ih  = (const float*)d_in[6];
    const float* b_hh  = (const float*)d_in[7];
    const float* v_w   = (const float*)d_in[20];
    const float* v_b   = (const float*)d_in[21];
    const float* dec_w = (const float*)d_in[22];
    const float* dec_b = (const float*)d_in[23];

    float* out  = (float*)d_out;
    float* hout = out + (size_t)SZ * 10;

    prep_kernel<<<(FRAG_TOTAL + 255) / 256, 256>>>(enc_w, w_ih, w_hh, v_w, dec_w);

    cudaFuncSetAttribute(ac_mma_kernel, cudaFuncAttributeMaxDynamicSharedMemorySize, SMEM_TOTAL);
    ac_mma_kernel<<<GRID, THREADS, SMEM_TOTAL>>>(obs, hid, enc_b, b_ih, b_hh, v_b, dec_b, out, hout);
}

// round 7
// speedup vs baseline: 6.0151x; 1.4346x over previous
#include <cuda_runtime.h>
#include <cuda_fp16.h>
#include <math.h>
#include <stdint.h>

#define SZ 65535
#define THREADS 256
#define GRID 512

// ---- weight fragment image offsets (uint4 units) ----
#define ENC_F   0        // 8 n2 x 16 kt x 32
#define WIHR_F  4096     // 8 n2 x 8 kt x 32
#define WIHZ_F  6144
#define WIHN_F  8192
#define WHHR_F  10240
#define WHHZ_F  12288
#define WHHN_F  14336
#define VW_F    16384    // 4 n2 x 8 kt x 32
#define DEC_F   17408    // 1 n2 x 12 kt x 32
#define FRAG_TOTAL 17792

__device__ __align__(16) uint4 g_bh[FRAG_TOTAL];   // fp16 weight fragments (single plane)

// ---- SMEM (bytes) ----
#define OFF_X    0        // 32KB: x (2 K blocks), later h_out
#define OFF_H    32768    // 32KB: h (2 K blocks); block0 later = v
#define OFF_OBS  65536    // 16KB: obs staging (enc phase only)
#define OFF_RZ   65536    // 33KB: packed sigma(r),sigma(z) fp16 (GRU phase, overlaps obs)
#define OFF_BR   99328
#define OFF_BZ   99840
#define OFF_BIN  100352
#define OFF_BHN  100864
#define OFF_ENCB 101376
#define OFF_VB   101888
#define OFF_DECB 102144
#define SMEM_TOTAL 102400

#define SWZ(o) ((o) ^ (((o) >> 3) & 0x70))
// rz stash: row-local 0..63, c2 0..63; stride 66 uint2 to spread banks
#define RZ_OFF(row, c2) ((uint32_t)(OFF_RZ + (((row) * 66 + (c2)) << 3)))

__device__ __forceinline__ uint32_t smem_u32(const void* p) {
    uint32_t a;
    asm("{ .reg .u64 t; cvta.to.shared.u64 t, %1; cvt.u32.u64 %0, t; }" : "=r"(a) : "l"(p));
    return a;
}

__device__ __forceinline__ void ldm4(uint32_t r[4], uint32_t a) {
    asm volatile("ldmatrix.sync.aligned.m8n8.x4.shared.b16 {%0,%1,%2,%3}, [%4];"
        : "=r"(r[0]), "=r"(r[1]), "=r"(r[2]), "=r"(r[3]) : "r"(a));
}

__device__ __forceinline__ void mma_f16(float c[4], const uint32_t a[4], uint32_t b0, uint32_t b1) {
    asm volatile("mma.sync.aligned.m16n8k16.row.col.f32.f16.f16.f32 "
        "{%0,%1,%2,%3}, {%4,%5,%6,%7}, {%8,%9}, {%0,%1,%2,%3};"
        : "+f"(c[0]), "+f"(c[1]), "+f"(c[2]), "+f"(c[3])
        : "r"(a[0]), "r"(a[1]), "r"(a[2]), "r"(a[3]), "r"(b0), "r"(b1));
}

__device__ __forceinline__ uint32_t packh2(float a, float b) {
    __half2 h = __floats2half2_rn(a, b);
    return *(uint32_t*)&h;
}
__device__ __forceinline__ float h_lo(uint32_t v) {
    return __half2float(__ushort_as_half((unsigned short)(v & 0xFFFF)));
}
__device__ __forceinline__ float h_hi(uint32_t v) {
    return __half2float(__ushort_as_half((unsigned short)(v >> 16)));
}

__device__ __forceinline__ float sigm(float x) { return 1.f / (1.f + __expf(-x)); }

__device__ __forceinline__ void store_pair(char* region, int row, int col, float a, float b) {
    uint32_t off = (uint32_t)((col >> 6) * 16384) + SWZ((uint32_t)(row * 128 + (col & 63) * 2));
    *(uint32_t*)(region + off) = packh2(a, b);
}

// [128 rows x 64 cols] fp32 gmem tile -> fp16 swizzled plane
__device__ void conv_tile(const float* __restrict__ g, int stride, int col0, int row0g,
                          char* dst, int tid) {
#pragma unroll
    for (int i = 0; i < 4; i++) {
        int t = tid + i * 256;
        int r = t >> 3, gi = t & 7;
        int gr = row0g + r;
        uint4 P;
        if (gr < SZ) {
            float4 a = *(const float4*)(g + (size_t)gr * stride + col0 + gi * 8);
            float4 b = *(const float4*)(g + (size_t)gr * stride + col0 + gi * 8 + 4);
            P.x = packh2(a.x, a.y); P.y = packh2(a.z, a.w);
            P.z = packh2(b.x, b.y); P.w = packh2(b.z, b.w);
        } else {
            P.x = P.y = P.z = P.w = 0u;
        }
        *(uint4*)(dst + SWZ((uint32_t)(r * 128 + gi * 16))) = P;
    }
}

// ---------------- prep: pack weights as fp16 mma B-fragments ----------------
__global__ void prep_kernel(const float* __restrict__ enc_w, const float* __restrict__ w_ih,
                            const float* __restrict__ w_hh, const float* __restrict__ v_w,
                            const float* __restrict__ dec_w) {
    int idx = blockIdx.x * blockDim.x + threadIdx.x;
    if (idx >= FRAG_TOTAL) return;
    const float* W; int ldw, nmax, ktc, base;
    if (idx < 4096)       { W = enc_w; ldw = 256; nmax = 128; base = 0; ktc = 16; }
    else if (idx < 10240) { int g = (idx - 4096) / 2048; W = w_ih + (size_t)g * 128 * 128;
                            ldw = 128; nmax = 128; base = 4096 + g * 2048; ktc = 8; }
    else if (idx < 16384) { int g = (idx - 10240) / 2048; W = w_hh + (size_t)g * 128 * 128;
                            ldw = 128; nmax = 128; base = 10240 + g * 2048; ktc = 8; }
    else if (idx < 17408) { W = v_w; ldw = 128; nmax = 64; base = 16384; ktc = 8; }
    else                  { W = dec_w; ldw = 192; nmax = 10; base = 17408; ktc = 12; }

    int local = idx - base;
    int n2 = local / (ktc * 32);
    int rem = local - n2 * ktc * 32;
    int kt = rem >> 5, lane = rem & 31;
    int n = n2 * 16 + (lane >> 2);
    int k = kt * 16 + (lane & 3) * 2;

    float w[8];
#pragma unroll
    for (int dn = 0; dn < 2; dn++)
#pragma unroll
        for (int dk = 0; dk < 2; dk++)
#pragma unroll
            for (int e = 0; e < 2; e++) {
                int nn = n + dn * 8, kk = k + dk * 8 + e;
                w[(dn + dk * 2) * 2 + e] = (nn < nmax) ? W[(size_t)nn * ldw + kk] : 0.f;
            }
    uint4 H;
    H.x = packh2(w[0], w[1]);
    H.y = packh2(w[2], w[3]);
    H.z = packh2(w[4], w[5]);
    H.w = packh2(w[6], w[7]);
    g_bh[idx] = H;
}

// n16-pair mma group (single weight plane): 2 mmas
__device__ __forceinline__ void mma1(float cE[4], float cO[4], const uint32_t a[4], uint4 Bh) {
    mma_f16(cE, a, Bh.x, Bh.z);
    mma_f16(cO, a, Bh.y, Bh.w);
}

// one A-source feeding TWO gate accumulators
__device__ __forceinline__ void gru_pass2(float (&A0)[8][4], float (&A1)[8][4],
                                          uint32_t areg, int mrow, int wn, int lane,
                                          int fb0, int fb1) {
    const int arow = mrow + (lane & 15);
    const int kkp = (lane >> 4) << 3;
#pragma unroll
    for (int kt = 0; kt < 8; kt++) {
        int kk = kt * 16 + kkp;
        uint4 B0[4], B1[4];
#pragma unroll
        for (int l = 0; l < 4; l++) B0[l] = g_bh[fb0 + ((wn * 4 + l) * 8 + kt) * 32 + lane];
#pragma unroll
        for (int l = 0; l < 4; l++) B1[l] = g_bh[fb1 + ((wn * 4 + l) * 8 + kt) * 32 + lane];
        uint32_t a[4];
        ldm4(a, areg + (uint32_t)((kk >> 6) * 16384) + SWZ((uint32_t)(arow * 128 + (kk & 63) * 2)));
#pragma unroll
        for (int l = 0; l < 4; l++) mma1(A0[2 * l], A0[2 * l + 1], a, B0[l]);
#pragma unroll
        for (int l = 0; l < 4; l++) mma1(A1[2 * l], A1[2 * l + 1], a, B1[l]);
    }
}

// one A-source feeding ONE gate accumulator
__device__ __forceinline__ void gru_pass1(float (&A0)[8][4],
                                          uint32_t areg, int mrow, int wn, int lane, int fb0) {
    const int arow = mrow + (lane & 15);
    const int kkp = (lane >> 4) << 3;
#pragma unroll
    for (int kt = 0; kt < 8; kt++) {
        int kk = kt * 16 + kkp;
        uint4 B0[4];
#pragma unroll
        for (int l = 0; l < 4; l++) B0[l] = g_bh[fb0 + ((wn * 4 + l) * 8 + kt) * 32 + lane];
        uint32_t a[4];
        ldm4(a, areg + (uint32_t)((kk >> 6) * 16384) + SWZ((uint32_t)(arow * 128 + (kk & 63) * 2)));
#pragma unroll
        for (int l = 0; l < 4; l++) mma1(A0[2 * l], A0[2 * l + 1], a, B0[l]);
    }
}

#define ZERO84(a) { _Pragma("unroll") for (int _i = 0; _i < 8; _i++) _Pragma("unroll") for (int _j = 0; _j < 4; _j++) (a)[_i][_j] = 0.f; }

__global__ void __launch_bounds__(THREADS, 2)
ac_mma_kernel(const float* __restrict__ obs, const float* __restrict__ hid,
              const float* __restrict__ enc_b, const float* __restrict__ b_ih,
              const float* __restrict__ b_hh, const float* __restrict__ v_b,
              const float* __restrict__ dec_b,
              float* __restrict__ out, float* __restrict__ hout_g) {
    extern __shared__ char sm[];
    const uint32_t sbase = smem_u32(sm);
    const int tid = threadIdx.x, lane = tid & 31, wid = tid >> 5;
    const int wm = wid & 3, wn = wid >> 2;
    const int row0 = blockIdx.x * 128;

    float* s_br   = (float*)(sm + OFF_BR);
    float* s_bz   = (float*)(sm + OFF_BZ);
    float* s_bin  = (float*)(sm + OFF_BIN);
    float* s_bhn  = (float*)(sm + OFF_BHN);
    float* s_encb = (float*)(sm + OFF_ENCB);
    float* s_vb   = (float*)(sm + OFF_VB);
    float* s_decb = (float*)(sm + OFF_DECB);

    if (tid < 128) {
        s_br[tid]   = b_ih[tid] + b_hh[tid];
        s_bz[tid]   = b_ih[128 + tid] + b_hh[128 + tid];
        s_bin[tid]  = b_ih[256 + tid];
        s_bhn[tid]  = b_hh[256 + tid];
        s_encb[tid] = enc_b[tid];
    }
    if (tid < 64) s_vb[tid]   = v_b[tid];
    if (tid < 16) s_decb[tid] = (tid < 10) ? dec_b[tid] : 0.f;

    // h -> fp16 plane (2 K blocks)
    conv_tile(hid, 128, 0,  row0, sm + OFF_H,         tid);
    conv_tile(hid, 128, 64, row0, sm + OFF_H + 16384, tid);

    const uint32_t xreg = sbase + OFF_X;
    const uint32_t hreg = sbase + OFF_H;
    const uint32_t oreg = sbase + OFF_OBS;
    const int kkp = (lane >> 4) << 3;

    // ======== enc GEMM: obs @ enc_w^T (K=256) ========
    {
        float acc[2][8][4];
#pragma unroll
        for (int mi = 0; mi < 2; mi++) ZERO84(acc[mi]);

        for (int kb = 0; kb < 4; kb++) {
            __syncthreads();
            conv_tile(obs, 256, kb * 64, row0, sm + OFF_OBS, tid);
            __syncthreads();
#pragma unroll
            for (int kt4 = 0; kt4 < 4; kt4++) {
                int ktg = kb * 4 + kt4;
                uint4 B[4];
#pragma unroll
                for (int l = 0; l < 4; l++)
                    B[l] = g_bh[ENC_F + ((wn * 4 + l) * 16 + ktg) * 32 + lane];
                uint32_t a[2][4];
#pragma unroll
                for (int mi = 0; mi < 2; mi++) {
                    int arow = wm * 32 + mi * 16 + (lane & 15);
                    ldm4(a[mi], oreg + SWZ((uint32_t)(arow * 128 + (kt4 * 16 + kkp) * 2)));
                }
#pragma unroll
                for (int l = 0; l < 4; l++)
#pragma unroll
                    for (int mi = 0; mi < 2; mi++)
                        mma1(acc[mi][2 * l], acc[mi][2 * l + 1], a[mi], B[l]);
            }
        }
        // x = relu(acc + b) -> s_x
        int rb = wm * 32 + (lane >> 2);
#pragma unroll
        for (int mi = 0; mi < 2; mi++)
#pragma unroll
            for (int ni = 0; ni < 8; ni++) {
                int col = wn * 64 + ni * 8 + (lane & 3) * 2;
                float b0 = s_encb[col], b1 = s_encb[col + 1];
#pragma unroll
                for (int rp = 0; rp < 2; rp++) {
                    int row = rb + mi * 16 + rp * 8;
                    store_pair(sm + OFF_X, row, col,
                               fmaxf(acc[mi][ni][rp * 2 + 0] + b0, 0.f),
                               fmaxf(acc[mi][ni][rp * 2 + 1] + b1, 0.f));
                }
            }
    }
    __syncthreads();

    // ======== GRU, two 64-row halves, each as (r,z) pass then (n) pass ========
    for (int hp = 0; hp < 2; hp++) {
        int mrow = hp * 64 + wm * 16;

        // ---- pass A: r,z ----
        {
            float rg[8][4], zg[8][4];
            ZERO84(rg); ZERO84(zg);
            gru_pass2(rg, zg, xreg, mrow, wn, lane, WIHR_F, WIHZ_F);
            gru_pass2(rg, zg, hreg, mrow, wn, lane, WHHR_F, WHHZ_F);
            int rbl = wm * 16 + (lane >> 2);
#pragma unroll
            for (int ni = 0; ni < 8; ni++) {
                int col = wn * 64 + ni * 8 + (lane & 3) * 2;
                int c2 = col >> 1;
                float br0 = s_br[col], br1 = s_br[col + 1];
                float bz0 = s_bz[col], bz1 = s_bz[col + 1];
#pragma unroll
                for (int rp = 0; rp < 2; rp++) {
                    int rl = rbl + rp * 8;
                    uint2 p;
                    p.x = packh2(sigm(rg[ni][rp * 2 + 0] + br0), sigm(rg[ni][rp * 2 + 1] + br1));
                    p.y = packh2(sigm(zg[ni][rp * 2 + 0] + bz0), sigm(zg[ni][rp * 2 + 1] + bz1));
                    *(uint2*)(sm + RZ_OFF(rl, c2)) = p;
                }
            }
        }

        // ---- pass B: a_n (from x), h_n (from h) ----
        {
            float an[8][4], hn[8][4];
            ZERO84(an); ZERO84(hn);
            gru_pass1(an, xreg, mrow, wn, lane, WIHN_F);
            gru_pass1(hn, hreg, mrow, wn, lane, WHHN_F);
            __syncthreads();   // all s_x reads of this half done before epilogue overwrites

            int rbl = wm * 16 + (lane >> 2);
#pragma unroll
            for (int ni = 0; ni < 8; ni++) {
                int col = wn * 64 + ni * 8 + (lane & 3) * 2;
                int c2 = col >> 1;
                float bi0 = s_bin[col], bi1 = s_bin[col + 1];
                float bh0 = s_bhn[col], bh1 = s_bhn[col + 1];
#pragma unroll
                for (int rp = 0; rp < 2; rp++) {
                    int rl = rbl + rp * 8;
                    int row = hp * 64 + rl;
                    int grow = row0 + row;
                    float h0 = 0.f, h1 = 0.f;
                    if (grow < SZ) {
                        float2 t = *(const float2*)(hid + (size_t)grow * 128 + col);
                        h0 = t.x; h1 = t.y;
                    }
                    uint2 p = *(const uint2*)(sm + RZ_OFF(rl, c2));
                    float r0 = h_lo(p.x), r1 = h_hi(p.x);
                    float z0 = h_lo(p.y), z1 = h_hi(p.y);
                    float n0 = tanhf(an[ni][rp * 2 + 0] + bi0 + r0 * (hn[ni][rp * 2 + 0] + bh0));
                    float n1 = tanhf(an[ni][rp * 2 + 1] + bi1 + r1 * (hn[ni][rp * 2 + 1] + bh1));
                    float o0 = (1.f - z0) * n0 + z0 * h0;
                    float o1 = (1.f - z1) * n1 + z1 * h1;
                    if (grow < SZ)
                        *(float2*)(hout_g + (size_t)grow * 128 + col) = make_float2(o0, o1);
                    store_pair(sm + OFF_X, row, col, o0, o1);
                }
            }
        }
        __syncthreads();
    }

    // ======== v GEMM: 128x64, A = h_out (s_x), K=128 ========
    {
        float vc[2][4][4];
#pragma unroll
        for (int mi = 0; mi < 2; mi++)
#pragma unroll
            for (int ni = 0; ni < 4; ni++)
#pragma unroll
                for (int j = 0; j < 4; j++) vc[mi][ni][j] = 0.f;
#pragma unroll
        for (int kt = 0; kt < 8; kt++) {
            int kk = kt * 16 + kkp;
            uint4 B[2];
#pragma unroll
            for (int l = 0; l < 2; l++)
                B[l] = g_bh[VW_F + ((wn * 2 + l) * 8 + kt) * 32 + lane];
            uint32_t a[2][4];
#pragma unroll
            for (int mi = 0; mi < 2; mi++) {
                int arow = wm * 32 + mi * 16 + (lane & 15);
                ldm4(a[mi], xreg + (uint32_t)((kk >> 6) * 16384) + SWZ((uint32_t)(arow * 128 + (kk & 63) * 2)));
            }
#pragma unroll
            for (int l = 0; l < 2; l++)
#pragma unroll
                for (int mi = 0; mi < 2; mi++)
                    mma1(vc[mi][2 * l], vc[mi][2 * l + 1], a[mi], B[l]);
        }
        // v -> s_h block 0
#pragma unroll
        for (int mi = 0; mi < 2; mi++)
#pragma unroll
            for (int ni = 0; ni < 4; ni++) {
                int col = wn * 32 + ni * 8 + (lane & 3) * 2;
                float b0 = s_vb[col], b1 = s_vb[col + 1];
#pragma unroll
                for (int rp = 0; rp < 2; rp++) {
                    int row = wm * 32 + mi * 16 + (lane >> 2) + rp * 8;
                    store_pair(sm + OFF_H, row, col,
                               fmaxf(vc[mi][ni][rp * 2 + 0] + b0, 0.f),
                               fmaxf(vc[mi][ni][rp * 2 + 1] + b1, 0.f));
                }
            }
    }
    __syncthreads();

    // ======== dec GEMM: [h_out | v] @ dec_w^T, K=192, N=16 ========
    {
        float dc[2][4];
#pragma unroll
        for (int mi = 0; mi < 2; mi++)
#pragma unroll
            for (int j = 0; j < 4; j++) dc[mi][j] = 0.f;
#pragma unroll
        for (int kt = 0; kt < 12; kt++) {
            uint32_t areg2 = (kt < 8) ? xreg : hreg;
            int kk = ((kt < 8) ? kt : (kt - 8)) * 16 + kkp;
            uint4 Bh = g_bh[DEC_F + kt * 32 + lane];
            uint32_t a[2][4];
#pragma unroll
            for (int mi = 0; mi < 2; mi++) {
                int arow = wm * 32 + mi * 16 + (lane & 15);
                ldm4(a[mi], areg2 + (uint32_t)((kk >> 6) * 16384) + SWZ((uint32_t)(arow * 128 + (kk & 63) * 2)));
            }
            uint32_t b0h = wn ? Bh.y : Bh.x, b1h = wn ? Bh.w : Bh.z;
#pragma unroll
            for (int mi = 0; mi < 2; mi++)
                mma_f16(dc[mi], a[mi], b0h, b1h);
        }
        int col = wn * 8 + (lane & 3) * 2;
        float b0 = s_decb[col], b1 = s_decb[col + 1];
#pragma unroll
        for (int mi = 0; mi < 2; mi++)
#pragma unroll
            for (int rp = 0; rp < 2; rp++) {
                int row = wm * 32 + mi * 16 + (lane >> 2) + rp * 8;
                int grow = row0 + row;
                if (grow < SZ) {
                    float o0 = dc[mi][rp * 2 + 0] + b0;
                    float o1 = dc[mi][rp * 2 + 1] + b1;
                    if (col < 10)     out[(size_t)grow * 10 + col] = o0;
                    if (col + 1 < 10) out[(size_t)grow * 10 + col + 1] = o1;
                }
            }
    }
}

extern "C" void kernel_launch(void* const* d_in, const int* in_sizes, int n_in,
                              void* d_out, int out_size) {
    const float* obs   = (const float*)d_in[0];
    const float* hid   = (const float*)d_in[1];
    const float* enc_w = (const float*)d_in[2];
    const float* enc_b = (const float*)d_in[3];
    const float* w_ih  = (const float*)d_in[4];
    const float* w_hh  = (const float*)d_in[5];
    const float* b_ih  = (const float*)d_in[6];
    const float* b_hh  = (const float*)d_in[7];
    const float* v_w   = (const float*)d_in[20];
    const float* v_b   = (const float*)d_in[21];
    const float* dec_w = (const float*)d_in[22];
    const float* dec_b = (const float*)d_in[23];

    float* out  = (float*)d_out;
    float* hout = out + (size_t)SZ * 10;

    prep_kernel<<<(FRAG_TOTAL + 255) / 256, 256>>>(enc_w, w_ih, w_hh, v_w, dec_w);

    cudaFuncSetAttribute(ac_mma_kernel, cudaFuncAttributeMaxDynamicSharedMemorySize, SMEM_TOTAL);
    ac_mma_kernel<<<GRID, THREADS, SMEM_TOTAL>>>(obs, hid, enc_b, b_ih, b_hh, v_b, dec_b, out, hout);
}

// round 8
// speedup vs baseline: 6.1730x; 1.0263x over previous
#include <cuda_runtime.h>
#include <cuda_fp16.h>
#include <math.h>
#include <stdint.h>

#define SZ 65535
#define THREADS 256
#define GRID 512

// ---- weight fragment image offsets (uint4 units) ----
#define ENC_F   0        // 8 n2 x 16 kt x 32
#define WIHR_F  4096     // 8 n2 x 8 kt x 32
#define WIHZ_F  6144
#define WIHN_F  8192
#define WHHR_F  10240
#define WHHZ_F  12288
#define WHHN_F  14336
#define VW_F    16384    // 4 n2 x 8 kt x 32
#define DEC_F   17408    // 1 n2 x 12 kt x 32
#define FRAG_TOTAL 17792

__device__ __align__(16) uint4 g_bh[FRAG_TOTAL];   // fp16 weight fragments (single plane)

// ---- SMEM (bytes) ----
#define OFF_X    0        // 32KB: x (2 K blocks), later h_out
#define OFF_H    32768    // 32KB: h (2 K blocks); block0 later = v
#define OFF_OBS  65536    // 2 x 16KB obs slots (enc phase only; slot1 overlaps RZ)
#define OFF_RZ   65536    // 33KB: packed sigma(r),sigma(z) fp16 (GRU phase)
#define OFF_BR   99328
#define OFF_BZ   99840
#define OFF_BIN  100352
#define OFF_BHN  100864
#define OFF_ENCB 101376
#define OFF_VB   101888
#define OFF_DECB 102144
#define SMEM_TOTAL 102400

#define SWZ(o) ((o) ^ (((o) >> 3) & 0x70))
// rz stash: row-local 0..63, c2 0..63; stride 66 uint2 to spread banks
#define RZ_OFF(row, c2) ((uint32_t)(OFF_RZ + (((row) * 66 + (c2)) << 3)))

__device__ __forceinline__ uint32_t smem_u32(const void* p) {
    uint32_t a;
    asm("{ .reg .u64 t; cvta.to.shared.u64 t, %1; cvt.u32.u64 %0, t; }" : "=r"(a) : "l"(p));
    return a;
}

__device__ __forceinline__ void ldm4(uint32_t r[4], uint32_t a) {
    asm volatile("ldmatrix.sync.aligned.m8n8.x4.shared.b16 {%0,%1,%2,%3}, [%4];"
        : "=r"(r[0]), "=r"(r[1]), "=r"(r[2]), "=r"(r[3]) : "r"(a));
}

__device__ __forceinline__ void mma_f16(float c[4], const uint32_t a[4], uint32_t b0, uint32_t b1) {
    asm volatile("mma.sync.aligned.m16n8k16.row.col.f32.f16.f16.f32 "
        "{%0,%1,%2,%3}, {%4,%5,%6,%7}, {%8,%9}, {%0,%1,%2,%3};"
        : "+f"(c[0]), "+f"(c[1]), "+f"(c[2]), "+f"(c[3])
        : "r"(a[0]), "r"(a[1]), "r"(a[2]), "r"(a[3]), "r"(b0), "r"(b1));
}

__device__ __forceinline__ uint32_t packh2(float a, float b) {
    __half2 h = __floats2half2_rn(a, b);
    return *(uint32_t*)&h;
}
__device__ __forceinline__ float h_lo(uint32_t v) {
    return __half2float(__ushort_as_half((unsigned short)(v & 0xFFFF)));
}
__device__ __forceinline__ float h_hi(uint32_t v) {
    return __half2float(__ushort_as_half((unsigned short)(v >> 16)));
}

__device__ __forceinline__ float sigm(float x) { return 1.f / (1.f + __expf(-x)); }

__device__ __forceinline__ void store_pair(char* region, int row, int col, float a, float b) {
    uint32_t off = (uint32_t)((col >> 6) * 16384) + SWZ((uint32_t)(row * 128 + (col & 63) * 2));
    *(uint32_t*)(region + off) = packh2(a, b);
}

// [128 rows x 64 cols] fp32 gmem tile -> fp16 swizzled plane (direct)
__device__ void conv_tile(const float* __restrict__ g, int stride, int col0, int row0g,
                          char* dst, int tid) {
#pragma unroll
    for (int i = 0; i < 4; i++) {
        int t = tid + i * 256;
        int r = t >> 3, gi = t & 7;
        int gr = row0g + r;
        uint4 P;
        if (gr < SZ) {
            float4 a = *(const float4*)(g + (size_t)gr * stride + col0 + gi * 8);
            float4 b = *(const float4*)(g + (size_t)gr * stride + col0 + gi * 8 + 4);
            P.x = packh2(a.x, a.y); P.y = packh2(a.z, a.w);
            P.z = packh2(b.x, b.y); P.w = packh2(b.z, b.w);
        } else {
            P.x = P.y = P.z = P.w = 0u;
        }
        *(uint4*)(dst + SWZ((uint32_t)(r * 128 + gi * 16))) = P;
    }
}

// double-buffer halves: load+pack into regs / store regs to smem
__device__ __forceinline__ void conv_load_pack(const float* __restrict__ g, int stride, int col0,
                                               int row0g, uint32_t st[16], int tid) {
#pragma unroll
    for (int i = 0; i < 4; i++) {
        int t = tid + i * 256;
        int r = t >> 3, gi = t & 7;
        int gr = row0g + r;
        if (gr < SZ) {
            float4 a = *(const float4*)(g + (size_t)gr * stride + col0 + gi * 8);
            float4 b = *(const float4*)(g + (size_t)gr * stride + col0 + gi * 8 + 4);
            st[i * 4 + 0] = packh2(a.x, a.y); st[i * 4 + 1] = packh2(a.z, a.w);
            st[i * 4 + 2] = packh2(b.x, b.y); st[i * 4 + 3] = packh2(b.z, b.w);
        } else {
            st[i * 4 + 0] = st[i * 4 + 1] = st[i * 4 + 2] = st[i * 4 + 3] = 0u;
        }
    }
}
__device__ __forceinline__ void conv_store16(char* dst, const uint32_t st[16], int tid) {
#pragma unroll
    for (int i = 0; i < 4; i++) {
        int t = tid + i * 256;
        int r = t >> 3, gi = t & 7;
        uint4 P = make_uint4(st[i * 4 + 0], st[i * 4 + 1], st[i * 4 + 2], st[i * 4 + 3]);
        *(uint4*)(dst + SWZ((uint32_t)(r * 128 + gi * 16))) = P;
    }
}

// ---------------- prep: pack weights as fp16 mma B-fragments ----------------
__global__ void prep_kernel(const float* __restrict__ enc_w, const float* __restrict__ w_ih,
                            const float* __restrict__ w_hh, const float* __restrict__ v_w,
                            const float* __restrict__ dec_w) {
    int idx = blockIdx.x * blockDim.x + threadIdx.x;
    if (idx >= FRAG_TOTAL) return;
    const float* W; int ldw, nmax, ktc, base;
    if (idx < 4096)       { W = enc_w; ldw = 256; nmax = 128; base = 0; ktc = 16; }
    else if (idx < 10240) { int g = (idx - 4096) / 2048; W = w_ih + (size_t)g * 128 * 128;
                            ldw = 128; nmax = 128; base = 4096 + g * 2048; ktc = 8; }
    else if (idx < 16384) { int g = (idx - 10240) / 2048; W = w_hh + (size_t)g * 128 * 128;
                            ldw = 128; nmax = 128; base = 10240 + g * 2048; ktc = 8; }
    else if (idx < 17408) { W = v_w; ldw = 128; nmax = 64; base = 16384; ktc = 8; }
    else                  { W = dec_w; ldw = 192; nmax = 10; base = 17408; ktc = 12; }

    int local = idx - base;
    int n2 = local / (ktc * 32);
    int rem = local - n2 * ktc * 32;
    int kt = rem >> 5, lane = rem & 31;
    int n = n2 * 16 + (lane >> 2);
    int k = kt * 16 + (lane & 3) * 2;

    float w[8];
#pragma unroll
    for (int dn = 0; dn < 2; dn++)
#pragma unroll
        for (int dk = 0; dk < 2; dk++)
#pragma unroll
            for (int e = 0; e < 2; e++) {
                int nn = n + dn * 8, kk = k + dk * 8 + e;
                w[(dn + dk * 2) * 2 + e] = (nn < nmax) ? W[(size_t)nn * ldw + kk] : 0.f;
            }
    uint4 H;
    H.x = packh2(w[0], w[1]);
    H.y = packh2(w[2], w[3]);
    H.z = packh2(w[4], w[5]);
    H.w = packh2(w[6], w[7]);
    g_bh[idx] = H;
}

// n16-pair mma group (single weight plane): 2 mmas
__device__ __forceinline__ void mma1(float cE[4], float cO[4], const uint32_t a[4], uint4 Bh) {
    mma_f16(cE, a, Bh.x, Bh.z);
    mma_f16(cO, a, Bh.y, Bh.w);
}

// precompute 8 swizzled ldmatrix addresses for one A source
__device__ __forceinline__ void make_addrs(uint32_t areg, int arow, int kkp, uint32_t ad[8]) {
#pragma unroll
    for (int kt = 0; kt < 8; kt++) {
        int kk = kt * 16 + kkp;
        ad[kt] = areg + (uint32_t)((kk >> 6) * 16384) + SWZ((uint32_t)(arow * 128 + (kk & 63) * 2));
    }
}

// one A-source feeding TWO gate accumulators
__device__ __forceinline__ void gru_pass2(float (&A0)[8][4], float (&A1)[8][4],
                                          const uint32_t ad[8], int wn, int lane,
                                          int fb0, int fb1) {
#pragma unroll
    for (int kt = 0; kt < 8; kt++) {
        uint4 B0[4], B1[4];
#pragma unroll
        for (int l = 0; l < 4; l++) B0[l] = g_bh[fb0 + ((wn * 4 + l) * 8 + kt) * 32 + lane];
#pragma unroll
        for (int l = 0; l < 4; l++) B1[l] = g_bh[fb1 + ((wn * 4 + l) * 8 + kt) * 32 + lane];
        uint32_t a[4];
        ldm4(a, ad[kt]);
#pragma unroll
        for (int l = 0; l < 4; l++) mma1(A0[2 * l], A0[2 * l + 1], a, B0[l]);
#pragma unroll
        for (int l = 0; l < 4; l++) mma1(A1[2 * l], A1[2 * l + 1], a, B1[l]);
    }
}

// one A-source feeding ONE gate accumulator
__device__ __forceinline__ void gru_pass1(float (&A0)[8][4],
                                          const uint32_t ad[8], int wn, int lane, int fb0) {
#pragma unroll
    for (int kt = 0; kt < 8; kt++) {
        uint4 B0[4];
#pragma unroll
        for (int l = 0; l < 4; l++) B0[l] = g_bh[fb0 + ((wn * 4 + l) * 8 + kt) * 32 + lane];
        uint32_t a[4];
        ldm4(a, ad[kt]);
#pragma unroll
        for (int l = 0; l < 4; l++) mma1(A0[2 * l], A0[2 * l + 1], a, B0[l]);
    }
}

#define ZERO84(a) { _Pragma("unroll") for (int _i = 0; _i < 8; _i++) _Pragma("unroll") for (int _j = 0; _j < 4; _j++) (a)[_i][_j] = 0.f; }

__global__ void __launch_bounds__(THREADS, 2)
ac_mma_kernel(const float* __restrict__ obs, const float* __restrict__ hid,
              const float* __restrict__ enc_b, const float* __restrict__ b_ih,
              const float* __restrict__ b_hh, const float* __restrict__ v_b,
              const float* __restrict__ dec_b,
              float* __restrict__ out, float* __restrict__ hout_g) {
    extern __shared__ char sm[];
    const uint32_t sbase = smem_u32(sm);
    const int tid = threadIdx.x, lane = tid & 31, wid = tid >> 5;
    const int wm = wid & 3, wn = wid >> 2;
    const int row0 = blockIdx.x * 128;

    float* s_br   = (float*)(sm + OFF_BR);
    float* s_bz   = (float*)(sm + OFF_BZ);
    float* s_bin  = (float*)(sm + OFF_BIN);
    float* s_bhn  = (float*)(sm + OFF_BHN);
    float* s_encb = (float*)(sm + OFF_ENCB);
    float* s_vb   = (float*)(sm + OFF_VB);
    float* s_decb = (float*)(sm + OFF_DECB);

    if (tid < 128) {
        s_br[tid]   = b_ih[tid] + b_hh[tid];
        s_bz[tid]   = b_ih[128 + tid] + b_hh[128 + tid];
        s_bin[tid]  = b_ih[256 + tid];
        s_bhn[tid]  = b_hh[256 + tid];
        s_encb[tid] = enc_b[tid];
    }
    if (tid < 64) s_vb[tid]   = v_b[tid];
    if (tid < 16) s_decb[tid] = (tid < 10) ? dec_b[tid] : 0.f;

    // h -> fp16 plane (2 K blocks)
    conv_tile(hid, 128, 0,  row0, sm + OFF_H,         tid);
    conv_tile(hid, 128, 64, row0, sm + OFF_H + 16384, tid);

    const uint32_t xreg = sbase + OFF_X;
    const uint32_t hreg = sbase + OFF_H;
    const uint32_t oreg = sbase + OFF_OBS;
    const int kkp = (lane >> 4) << 3;

    // ======== enc GEMM: obs @ enc_w^T (K=256), double-buffered obs stream ========
    {
        float acc[2][8][4];
#pragma unroll
        for (int mi = 0; mi < 2; mi++) ZERO84(acc[mi]);

        conv_tile(obs, 256, 0, row0, sm + OFF_OBS, tid);   // chunk 0 -> slot 0
        __syncthreads();

        uint32_t st[16];
        for (int kb = 0; kb < 4; kb++) {
            const uint32_t slotr = oreg + (uint32_t)((kb & 1) * 16384);
            if (kb < 3) conv_load_pack(obs, 256, (kb + 1) * 64, row0, st, tid);
#pragma unroll
            for (int kt4 = 0; kt4 < 4; kt4++) {
                int ktg = kb * 4 + kt4;
                uint4 B[4];
#pragma unroll
                for (int l = 0; l < 4; l++)
                    B[l] = g_bh[ENC_F + ((wn * 4 + l) * 16 + ktg) * 32 + lane];
                uint32_t a[2][4];
#pragma unroll
                for (int mi = 0; mi < 2; mi++) {
                    int arow = wm * 32 + mi * 16 + (lane & 15);
                    ldm4(a[mi], slotr + SWZ((uint32_t)(arow * 128 + (kt4 * 16 + kkp) * 2)));
                }
#pragma unroll
                for (int l = 0; l < 4; l++)
#pragma unroll
                    for (int mi = 0; mi < 2; mi++)
                        mma1(acc[mi][2 * l], acc[mi][2 * l + 1], a[mi], B[l]);
            }
            if (kb < 3) conv_store16(sm + OFF_OBS + (((kb + 1) & 1) * 16384), st, tid);
            __syncthreads();
        }

        // x = relu(acc + b) -> s_x
        int rb = wm * 32 + (lane >> 2);
#pragma unroll
        for (int mi = 0; mi < 2; mi++)
#pragma unroll
            for (int ni = 0; ni < 8; ni++) {
                int col = wn * 64 + ni * 8 + (lane & 3) * 2;
                float b0 = s_encb[col], b1 = s_encb[col + 1];
#pragma unroll
                for (int rp = 0; rp < 2; rp++) {
                    int row = rb + mi * 16 + rp * 8;
                    store_pair(sm + OFF_X, row, col,
                               fmaxf(acc[mi][ni][rp * 2 + 0] + b0, 0.f),
                               fmaxf(acc[mi][ni][rp * 2 + 1] + b1, 0.f));
                }
            }
    }
    __syncthreads();

    // ======== GRU, two 64-row halves, each as (r,z) pass then (n) pass ========
    for (int hp = 0; hp < 2; hp++) {
        int mrow = hp * 64 + wm * 16;
        uint32_t ax[8], ah[8];
        make_addrs(xreg, mrow + (lane & 15), kkp, ax);
        make_addrs(hreg, mrow + (lane & 15), kkp, ah);

        // ---- pass A: r,z ----
        {
            float rg[8][4], zg[8][4];
            ZERO84(rg); ZERO84(zg);
            gru_pass2(rg, zg, ax, wn, lane, WIHR_F, WIHZ_F);
            gru_pass2(rg, zg, ah, wn, lane, WHHR_F, WHHZ_F);
            int rbl = wm * 16 + (lane >> 2);
#pragma unroll
            for (int ni = 0; ni < 8; ni++) {
                int col = wn * 64 + ni * 8 + (lane & 3) * 2;
                int c2 = col >> 1;
                float br0 = s_br[col], br1 = s_br[col + 1];
                float bz0 = s_bz[col], bz1 = s_bz[col + 1];
#pragma unroll
                for (int rp = 0; rp < 2; rp++) {
                    int rl = rbl + rp * 8;
                    uint2 p;
                    p.x = packh2(sigm(rg[ni][rp * 2 + 0] + br0), sigm(rg[ni][rp * 2 + 1] + br1));
                    p.y = packh2(sigm(zg[ni][rp * 2 + 0] + bz0), sigm(zg[ni][rp * 2 + 1] + bz1));
                    *(uint2*)(sm + RZ_OFF(rl, c2)) = p;
                }
            }
        }

        // ---- pass B: a_n (from x), h_n (from h) ----
        {
            float an[8][4], hn[8][4];
            ZERO84(an); ZERO84(hn);
            gru_pass1(an, ax, wn, lane, WIHN_F);
            gru_pass1(hn, ah, wn, lane, WHHN_F);
            __syncthreads();   // all s_x reads of this half done before epilogue overwrites

            int rbl = wm * 16 + (lane >> 2);
#pragma unroll
            for (int ni = 0; ni < 8; ni++) {
                int col = wn * 64 + ni * 8 + (lane & 3) * 2;
                int c2 = col >> 1;
                float bi0 = s_bin[col], bi1 = s_bin[col + 1];
                float bh0 = s_bhn[col], bh1 = s_bhn[col + 1];
#pragma unroll
                for (int rp = 0; rp < 2; rp++) {
                    int rl = rbl + rp * 8;
                    int row = hp * 64 + rl;
                    int grow = row0 + row;
                    float h0 = 0.f, h1 = 0.f;
                    if (grow < SZ) {
                        float2 t = *(const float2*)(hid + (size_t)grow * 128 + col);
                        h0 = t.x; h1 = t.y;
                    }
                    uint2 p = *(const uint2*)(sm + RZ_OFF(rl, c2));
                    float r0 = h_lo(p.x), r1 = h_hi(p.x);
                    float z0 = h_lo(p.y), z1 = h_hi(p.y);
                    float n0 = tanhf(an[ni][rp * 2 + 0] + bi0 + r0 * (hn[ni][rp * 2 + 0] + bh0));
                    float n1 = tanhf(an[ni][rp * 2 + 1] + bi1 + r1 * (hn[ni][rp * 2 + 1] + bh1));
                    float o0 = (1.f - z0) * n0 + z0 * h0;
                    float o1 = (1.f - z1) * n1 + z1 * h1;
                    if (grow < SZ)
                        *(float2*)(hout_g + (size_t)grow * 128 + col) = make_float2(o0, o1);
                    store_pair(sm + OFF_X, row, col, o0, o1);
                }
            }
        }
        __syncthreads();
    }

    // ======== v GEMM: 128x64, A = h_out (s_x), K=128 ========
    {
        float vc[2][4][4];
#pragma unroll
        for (int mi = 0; mi < 2; mi++)
#pragma unroll
            for (int ni = 0; ni < 4; ni++)
#pragma unroll
                for (int j = 0; j < 4; j++) vc[mi][ni][j] = 0.f;
#pragma unroll
        for (int kt = 0; kt < 8; kt++) {
            int kk = kt * 16 + kkp;
            uint4 B[2];
#pragma unroll
            for (int l = 0; l < 2; l++)
                B[l] = g_bh[VW_F + ((wn * 2 + l) * 8 + kt) * 32 + lane];
            uint32_t a[2][4];
#pragma unroll
            for (int mi = 0; mi < 2; mi++) {
                int arow = wm * 32 + mi * 16 + (lane & 15);
                ldm4(a[mi], xreg + (uint32_t)((kk >> 6) * 16384) + SWZ((uint32_t)(arow * 128 + (kk & 63) * 2)));
            }
#pragma unroll
            for (int l = 0; l < 2; l++)
#pragma unroll
                for (int mi = 0; mi < 2; mi++)
                    mma1(vc[mi][2 * l], vc[mi][2 * l + 1], a[mi], B[l]);
        }
        // v -> s_h block 0
#pragma unroll
        for (int mi = 0; mi < 2; mi++)
#pragma unroll
            for (int ni = 0; ni < 4; ni++) {
                int col = wn * 32 + ni * 8 + (lane & 3) * 2;
                float b0 = s_vb[col], b1 = s_vb[col + 1];
#pragma unroll
                for (int rp = 0; rp < 2; rp++) {
                    int row = wm * 32 + mi * 16 + (lane >> 2) + rp * 8;
                    store_pair(sm + OFF_H, row, col,
                               fmaxf(vc[mi][ni][rp * 2 + 0] + b0, 0.f),
                               fmaxf(vc[mi][ni][rp * 2 + 1] + b1, 0.f));
                }
            }
    }
    __syncthreads();

    // ======== dec GEMM: [h_out | v] @ dec_w^T, K=192, N=16 ========
    {
        float dc[2][4];
#pragma unroll
        for (int mi = 0; mi < 2; mi++)
#pragma unroll
            for (int j = 0; j < 4; j++) dc[mi][j] = 0.f;
#pragma unroll
        for (int kt = 0; kt < 12; kt++) {
            uint32_t areg2 = (kt < 8) ? xreg : hreg;
            int kk = ((kt < 8) ? kt : (kt - 8)) * 16 + kkp;
            uint4 Bh = g_bh[DEC_F + kt * 32 + lane];
            uint32_t a[2][4];
#pragma unroll
            for (int mi = 0; mi < 2; mi++) {
                int arow = wm * 32 + mi * 16 + (lane & 15);
                ldm4(a[mi], areg2 + (uint32_t)((kk >> 6) * 16384) + SWZ((uint32_t)(arow * 128 + (kk & 63) * 2)));
            }
            uint32_t b0h = wn ? Bh.y : Bh.x, b1h = wn ? Bh.w : Bh.z;
#pragma unroll
            for (int mi = 0; mi < 2; mi++)
                mma_f16(dc[mi], a[mi], b0h, b1h);
        }
        int col = wn * 8 + (lane & 3) * 2;
        float b0 = s_decb[col], b1 = s_decb[col + 1];
#pragma unroll
        for (int mi = 0; mi < 2; mi++)
#pragma unroll
            for (int rp = 0; rp < 2; rp++) {
                int row = wm * 32 + mi * 16 + (lane >> 2) + rp * 8;
                int grow = row0 + row;
                if (grow < SZ) {
                    float o0 = dc[mi][rp * 2 + 0] + b0;
                    float o1 = dc[mi][rp * 2 + 1] + b1;
                    if (col < 10)     out[(size_t)grow * 10 + col] = o0;
                    if (col + 1 < 10) out[(size_t)grow * 10 + col + 1] = o1;
                }
            }
    }
}

extern "C" void kernel_launch(void* const* d_in, const int* in_sizes, int n_in,
                              void* d_out, int out_size) {
    const float* obs   = (const float*)d_in[0];
    const float* hid   = (const float*)d_in[1];
    const float* enc_w = (const float*)d_in[2];
    const float* enc_b = (const float*)d_in[3];
    const float* w_ih  = (const float*)d_in[4];
    const float* w_hh  = (const float*)d_in[5];
    const float* b_ih  = (const float*)d_in[6];
    const float* b_hh  = (const float*)d_in[7];
    const float* v_w   = (const float*)d_in[20];
    const float* v_b   = (const float*)d_in[21];
    const float* dec_w = (const float*)d_in[22];
    const float* dec_b = (const float*)d_in[23];

    float* out  = (float*)d_out;
    float* hout = out + (size_t)SZ * 10;

    prep_kernel<<<(FRAG_TOTAL + 255) / 256, 256>>>(enc_w, w_ih, w_hh, v_w, dec_w);

    cudaFuncSetAttribute(ac_mma_kernel, cudaFuncAttributeMaxDynamicSharedMemorySize, SMEM_TOTAL);
    ac_mma_kernel<<<GRID, THREADS, SMEM_TOTAL>>>(obs, hid, enc_b, b_ih, b_hh, v_b, dec_b, out, hout);
}